// round 1
// baseline (speedup 1.0000x reference)
#include <cuda_runtime.h>
#include <math.h>

// Problem constants
#define BATCH 4
#define SEQ   1024
#define EMB   2048
#define HEADS 16
#define HDIM  128
#define MTOK  (BATCH * SEQ)      // 4096
#define QKVN  (3 * EMB)          // 6144

// Scratch (device globals: no cudaMalloc allowed)
__device__ float g_q[BATCH * HEADS * SEQ * HDIM];
__device__ float g_k[BATCH * HEADS * SEQ * HDIM];
__device__ float g_v[BATCH * HEADS * SEQ * HDIM];
__device__ float g_ctx[(size_t)MTOK * EMB];

// ============================================================================
// SGEMM-NT: C[m,n] = sum_k A[m,k] * B[n,k] + bias[n]
// A: [M,K] row-major, B: [N,K] row-major. 128x128x8 tiles, 8x8 per thread,
// double-buffered smem, padded stride 132 for conflict-free transposed stores.
// mode 0: write C0[m*N + n]  (row-major, + bias)
// mode 1: QKV scatter: n in [0,6144): part=n/2048 -> {C0,C1,C2}, head layout
//         dst[((b*H + h)*S + s)*D + d],  d = n % 128 (tile-aligned).
// ============================================================================
__global__ __launch_bounds__(256, 2)
void sgemm_nt_kernel(const float* __restrict__ A,
                     const float* __restrict__ Bw,
                     const float* __restrict__ bias,
                     float* __restrict__ C0,
                     float* __restrict__ C1,
                     float* __restrict__ C2,
                     int M, int N, int K, int mode)
{
    __shared__ float As[2][8][132];
    __shared__ float Bs[2][8][132];

    const int tid = threadIdx.x;
    const int tx  = tid & 15;
    const int ty  = tid >> 4;
    const int m0  = blockIdx.y << 7;
    const int n0  = blockIdx.x << 7;

    // global-load assignment: 256 threads load 128 rows x 8 k (2 float4 / row)
    const int lrow = tid >> 1;           // 0..127
    const int lk   = (tid & 1) << 2;     // 0 or 4

    const float* Ap = A  + (size_t)(m0 + lrow) * K + lk;
    const float* Bp = Bw + (size_t)(n0 + lrow) * K + lk;

    float4 ar = *(const float4*)Ap;
    float4 br = *(const float4*)Bp;

    float acc[8][8];
#pragma unroll
    for (int i = 0; i < 8; ++i)
#pragma unroll
        for (int j = 0; j < 8; ++j) acc[i][j] = 0.f;

    As[0][lk + 0][lrow] = ar.x; As[0][lk + 1][lrow] = ar.y;
    As[0][lk + 2][lrow] = ar.z; As[0][lk + 3][lrow] = ar.w;
    Bs[0][lk + 0][lrow] = br.x; Bs[0][lk + 1][lrow] = br.y;
    Bs[0][lk + 2][lrow] = br.z; Bs[0][lk + 3][lrow] = br.w;
    __syncthreads();

    const int ntiles = K >> 3;
    int buf = 0;
    for (int t = 0; t < ntiles; ++t) {
        if (t + 1 < ntiles) {
            ar = *(const float4*)(Ap + (size_t)(t + 1) * 8);
            br = *(const float4*)(Bp + (size_t)(t + 1) * 8);
        }
#pragma unroll
        for (int k = 0; k < 8; ++k) {
            float a[8], b[8];
            *(float4*)&a[0] = *(const float4*)&As[buf][k][ty * 4];
            *(float4*)&a[4] = *(const float4*)&As[buf][k][64 + ty * 4];
            *(float4*)&b[0] = *(const float4*)&Bs[buf][k][tx * 4];
            *(float4*)&b[4] = *(const float4*)&Bs[buf][k][64 + tx * 4];
#pragma unroll
            for (int i = 0; i < 8; ++i)
#pragma unroll
                for (int j = 0; j < 8; ++j)
                    acc[i][j] = fmaf(a[i], b[j], acc[i][j]);
        }
        if (t + 1 < ntiles) {
            buf ^= 1;
            As[buf][lk + 0][lrow] = ar.x; As[buf][lk + 1][lrow] = ar.y;
            As[buf][lk + 2][lrow] = ar.z; As[buf][lk + 3][lrow] = ar.w;
            Bs[buf][lk + 0][lrow] = br.x; Bs[buf][lk + 1][lrow] = br.y;
            Bs[buf][lk + 2][lrow] = br.z; Bs[buf][lk + 3][lrow] = br.w;
            __syncthreads();
        }
    }

    // bias for this thread's 8 columns (quadrant layout)
    float bv[8];
#pragma unroll
    for (int j = 0; j < 8; ++j) {
        int cl = (j < 4) ? (tx * 4 + j) : (64 + tx * 4 + (j - 4));
        bv[j] = bias[n0 + cl];
    }

    if (mode == 0) {
#pragma unroll
        for (int i = 0; i < 8; ++i) {
            int r = m0 + ((i < 4) ? (ty * 4 + i) : (64 + ty * 4 + (i - 4)));
            float4 o0 = make_float4(acc[i][0] + bv[0], acc[i][1] + bv[1],
                                    acc[i][2] + bv[2], acc[i][3] + bv[3]);
            float4 o1 = make_float4(acc[i][4] + bv[4], acc[i][5] + bv[5],
                                    acc[i][6] + bv[6], acc[i][7] + bv[7]);
            *(float4*)&C0[(size_t)r * N + n0 + tx * 4]       = o0;
            *(float4*)&C0[(size_t)r * N + n0 + 64 + tx * 4]  = o1;
        }
    } else {
        // whole 128-col tile lies in exactly one (part, head)
        const int part = n0 >> 11;            // n0 / 2048
        const int h    = (n0 & 2047) >> 7;    // (n0 % 2048) / 128
        float* dst = (part == 0) ? C0 : (part == 1) ? C1 : C2;
#pragma unroll
        for (int i = 0; i < 8; ++i) {
            int r  = m0 + ((i < 4) ? (ty * 4 + i) : (64 + ty * 4 + (i - 4)));
            int bb = r >> 10;                 // r / 1024
            int ss = r & 1023;
            size_t base = (((size_t)(bb * HEADS + h) * SEQ) + ss) * HDIM;
            float4 o0 = make_float4(acc[i][0] + bv[0], acc[i][1] + bv[1],
                                    acc[i][2] + bv[2], acc[i][3] + bv[3]);
            float4 o1 = make_float4(acc[i][4] + bv[4], acc[i][5] + bv[5],
                                    acc[i][6] + bv[6], acc[i][7] + bv[7]);
            *(float4*)&dst[base + tx * 4]      = o0;
            *(float4*)&dst[base + 64 + tx * 4] = o1;
        }
    }
}

// ============================================================================
// Flash attention (fp32, non-causal). One block = one (b,h) x 64 q-rows.
// 256 threads (16x16). S-gemm: 4x4 per thread; PV-gemm: 4 rows x 8 cols.
// Online softmax with per-row stats replicated across the 16 tx lanes.
// ============================================================================
#define QKV_STRIDE 132
#define PS_STRIDE  68
#define FLASH_SMEM ((3 * 64 * QKV_STRIDE + 64 * PS_STRIDE) * (int)sizeof(float))

__global__ __launch_bounds__(256, 1)
void flash_attn_kernel(const float* __restrict__ Qg,
                       const float* __restrict__ Kg,
                       const float* __restrict__ Vg,
                       float* __restrict__ Cg)
{
    extern __shared__ float sm[];
    float* Qs = sm;                               // 64 x 132
    float* Ks = Qs + 64 * QKV_STRIDE;             // 64 x 132
    float* Vs = Ks + 64 * QKV_STRIDE;             // 64 x 132
    float* Ps = Vs + 64 * QKV_STRIDE;             // 64 x 68

    const int bh = blockIdx.x;                    // 0..63
    const int q0 = blockIdx.y << 6;
    const int b  = bh >> 4;
    const int h  = bh & 15;
    const float* Qp = Qg + (size_t)bh * SEQ * HDIM;
    const float* Kp = Kg + (size_t)bh * SEQ * HDIM;
    const float* Vp = Vg + (size_t)bh * SEQ * HDIM;

    const int tid = threadIdx.x;
    const int tx  = tid & 15;
    const int ty  = tid >> 4;
    const float scale = 0.088388347648318447f;    // 1/sqrt(128)

    // load Q tile (pre-scaled)
    for (int i = tid; i < 2048; i += 256) {       // 2048 float4 = 64x128
        int r = i >> 5, c = (i & 31) << 2;
        float4 v = *(const float4*)&Qp[(size_t)(q0 + r) * HDIM + c];
        v.x *= scale; v.y *= scale; v.z *= scale; v.w *= scale;
        *(float4*)&Qs[r * QKV_STRIDE + c] = v;
    }

    float O[4][8];
    float m_[4], l_[4];
#pragma unroll
    for (int i = 0; i < 4; ++i) {
        m_[i] = -INFINITY; l_[i] = 0.f;
#pragma unroll
        for (int j = 0; j < 8; ++j) O[i][j] = 0.f;
    }

    for (int kv0 = 0; kv0 < SEQ; kv0 += 64) {
        __syncthreads();   // previous iter done reading Ks/Vs/Ps (also covers Q load)
        for (int i = tid; i < 2048; i += 256) {
            int r = i >> 5, c = (i & 31) << 2;
            *(float4*)&Ks[r * QKV_STRIDE + c] =
                *(const float4*)&Kp[(size_t)(kv0 + r) * HDIM + c];
            *(float4*)&Vs[r * QKV_STRIDE + c] =
                *(const float4*)&Vp[(size_t)(kv0 + r) * HDIM + c];
        }
        __syncthreads();

        // S = (Q*scale) K^T, 4x4 per thread: rows ty*4+i, cols tx*4+j
        float sacc[4][4];
#pragma unroll
        for (int i = 0; i < 4; ++i)
#pragma unroll
            for (int j = 0; j < 4; ++j) sacc[i][j] = 0.f;

        for (int d0 = 0; d0 < HDIM; d0 += 4) {
            float4 q4[4], k4[4];
#pragma unroll
            for (int i = 0; i < 4; ++i)
                q4[i] = *(const float4*)&Qs[(ty * 4 + i) * QKV_STRIDE + d0];
#pragma unroll
            for (int j = 0; j < 4; ++j)
                k4[j] = *(const float4*)&Ks[(tx * 4 + j) * QKV_STRIDE + d0];
#pragma unroll
            for (int i = 0; i < 4; ++i)
#pragma unroll
                for (int j = 0; j < 4; ++j) {
                    sacc[i][j] = fmaf(q4[i].x, k4[j].x, sacc[i][j]);
                    sacc[i][j] = fmaf(q4[i].y, k4[j].y, sacc[i][j]);
                    sacc[i][j] = fmaf(q4[i].z, k4[j].z, sacc[i][j]);
                    sacc[i][j] = fmaf(q4[i].w, k4[j].w, sacc[i][j]);
                }
        }

        // online softmax per row (reduce across the 16 tx lanes; lanes
        // ty*16+tx sit in 16-lane shuffle segments)
#pragma unroll
        for (int i = 0; i < 4; ++i) {
            float mx = fmaxf(fmaxf(sacc[i][0], sacc[i][1]),
                             fmaxf(sacc[i][2], sacc[i][3]));
            mx = fmaxf(mx, __shfl_xor_sync(0xffffffffu, mx, 1, 16));
            mx = fmaxf(mx, __shfl_xor_sync(0xffffffffu, mx, 2, 16));
            mx = fmaxf(mx, __shfl_xor_sync(0xffffffffu, mx, 4, 16));
            mx = fmaxf(mx, __shfl_xor_sync(0xffffffffu, mx, 8, 16));
            float mnew  = fmaxf(m_[i], mx);
            float alpha = __expf(m_[i] - mnew);
            m_[i] = mnew;
            float p0 = __expf(sacc[i][0] - mnew);
            float p1 = __expf(sacc[i][1] - mnew);
            float p2 = __expf(sacc[i][2] - mnew);
            float p3 = __expf(sacc[i][3] - mnew);
            float rs = (p0 + p1) + (p2 + p3);
            rs += __shfl_xor_sync(0xffffffffu, rs, 1, 16);
            rs += __shfl_xor_sync(0xffffffffu, rs, 2, 16);
            rs += __shfl_xor_sync(0xffffffffu, rs, 4, 16);
            rs += __shfl_xor_sync(0xffffffffu, rs, 8, 16);
            l_[i] = l_[i] * alpha + rs;
#pragma unroll
            for (int j = 0; j < 8; ++j) O[i][j] *= alpha;
            float* pr = &Ps[(ty * 4 + i) * PS_STRIDE + tx * 4];
            pr[0] = p0; pr[1] = p1; pr[2] = p2; pr[3] = p3;
        }
        __syncthreads();

        // O += P V : rows ty*4+i, cols {tx*4..+3, 64+tx*4..+3}
        for (int jj = 0; jj < 64; ++jj) {
            float p[4];
#pragma unroll
            for (int i = 0; i < 4; ++i)
                p[i] = Ps[(ty * 4 + i) * PS_STRIDE + jj];
            float4 v0 = *(const float4*)&Vs[jj * QKV_STRIDE + tx * 4];
            float4 v1 = *(const float4*)&Vs[jj * QKV_STRIDE + 64 + tx * 4];
#pragma unroll
            for (int i = 0; i < 4; ++i) {
                O[i][0] = fmaf(p[i], v0.x, O[i][0]);
                O[i][1] = fmaf(p[i], v0.y, O[i][1]);
                O[i][2] = fmaf(p[i], v0.z, O[i][2]);
                O[i][3] = fmaf(p[i], v0.w, O[i][3]);
                O[i][4] = fmaf(p[i], v1.x, O[i][4]);
                O[i][5] = fmaf(p[i], v1.y, O[i][5]);
                O[i][6] = fmaf(p[i], v1.z, O[i][6]);
                O[i][7] = fmaf(p[i], v1.w, O[i][7]);
            }
        }
    }

    // normalize and write ctx in [B,S,E] layout for the out-proj GEMM
#pragma unroll
    for (int i = 0; i < 4; ++i) {
        float inv = 1.f / l_[i];
        int token = b * SEQ + q0 + ty * 4 + i;
        float* op = Cg + (size_t)token * EMB + h * HDIM;
        float4 o0 = make_float4(O[i][0] * inv, O[i][1] * inv,
                                O[i][2] * inv, O[i][3] * inv);
        float4 o1 = make_float4(O[i][4] * inv, O[i][5] * inv,
                                O[i][6] * inv, O[i][7] * inv);
        *(float4*)&op[tx * 4]      = o0;
        *(float4*)&op[64 + tx * 4] = o1;
    }
}

// ============================================================================
// Launch
// ============================================================================
extern "C" void kernel_launch(void* const* d_in, const int* in_sizes, int n_in,
                              void* d_out, int out_size)
{
    (void)in_sizes; (void)n_in; (void)out_size;
    const float* x     = (const float*)d_in[0];  // query [B,S,E]
    const float* w_in  = (const float*)d_in[1];  // [3E, E]
    const float* b_in  = (const float*)d_in[2];  // [3E]
    const float* w_out = (const float*)d_in[3];  // [E, E]
    const float* b_out = (const float*)d_in[4];  // [E]
    float* out = (float*)d_out;                  // [B,S,E]

    float *qp, *kp, *vp, *cp;
    cudaGetSymbolAddress((void**)&qp, g_q);
    cudaGetSymbolAddress((void**)&kp, g_k);
    cudaGetSymbolAddress((void**)&vp, g_v);
    cudaGetSymbolAddress((void**)&cp, g_ctx);

    cudaFuncSetAttribute(flash_attn_kernel,
                         cudaFuncAttributeMaxDynamicSharedMemorySize, FLASH_SMEM);

    // 1) fused QKV projection, scattered into [B,H,S,D] per head
    dim3 g1(QKVN / 128, MTOK / 128);
    sgemm_nt_kernel<<<g1, 256>>>(x, w_in, b_in, qp, kp, vp,
                                 MTOK, QKVN, EMB, 1);

    // 2) flash attention -> ctx [B,S,E]
    dim3 g2(BATCH * HEADS, SEQ / 64);
    flash_attn_kernel<<<g2, 256, FLASH_SMEM>>>(qp, kp, vp, cp);

    // 3) output projection
    dim3 g3(EMB / 128, MTOK / 128);
    sgemm_nt_kernel<<<g3, 256>>>(cp, w_out, b_out, out, nullptr, nullptr,
                                 MTOK, EMB, EMB, 0);
}

// round 2
// speedup vs baseline: 1.0008x; 1.0008x over previous
#include <cuda_runtime.h>
#include <math.h>

// Problem constants
#define BATCH 4
#define SEQ   1024
#define EMB   2048
#define HEADS 16
#define HDIM  128
#define MTOK  (BATCH * SEQ)      // 4096
#define QKVN  (3 * EMB)          // 6144

// Scratch (device globals: no cudaMalloc allowed)
__device__ float g_q[BATCH * HEADS * SEQ * HDIM];
__device__ float g_k[BATCH * HEADS * SEQ * HDIM];
__device__ float g_v[BATCH * HEADS * SEQ * HDIM];
__device__ float g_ctx[(size_t)MTOK * EMB];

// ============================================================================
// SGEMM-NT: C[m,n] = sum_k A[m,k] * B[n,k] + bias[n]
// A: [M,K] row-major, B: [N,K] row-major. 128x128x8 tiles, 8x8 per thread,
// double-buffered smem, padded stride 132 for conflict-free transposed stores.
// mode 0: write C0[m*N + n]  (row-major, + bias)
// mode 1: QKV scatter: n in [0,6144): part=n/2048 -> {C0,C1,C2}, head layout
//         dst[((b*H + h)*S + s)*D + d],  d = n % 128 (tile-aligned).
// ============================================================================
__global__ __launch_bounds__(256, 2)
void sgemm_nt_kernel(const float* __restrict__ A,
                     const float* __restrict__ Bw,
                     const float* __restrict__ bias,
                     float* __restrict__ C0,
                     float* __restrict__ C1,
                     float* __restrict__ C2,
                     int M, int N, int K, int mode)
{
    __shared__ float As[2][8][132];
    __shared__ float Bs[2][8][132];

    const int tid = threadIdx.x;
    const int tx  = tid & 15;
    const int ty  = tid >> 4;
    const int m0  = blockIdx.y << 7;
    const int n0  = blockIdx.x << 7;

    // global-load assignment: 256 threads load 128 rows x 8 k (2 float4 / row)
    const int lrow = tid >> 1;           // 0..127
    const int lk   = (tid & 1) << 2;     // 0 or 4

    const float* Ap = A  + (size_t)(m0 + lrow) * K + lk;
    const float* Bp = Bw + (size_t)(n0 + lrow) * K + lk;

    float4 ar = *(const float4*)Ap;
    float4 br = *(const float4*)Bp;

    float acc[8][8];
#pragma unroll
    for (int i = 0; i < 8; ++i)
#pragma unroll
        for (int j = 0; j < 8; ++j) acc[i][j] = 0.f;

    As[0][lk + 0][lrow] = ar.x; As[0][lk + 1][lrow] = ar.y;
    As[0][lk + 2][lrow] = ar.z; As[0][lk + 3][lrow] = ar.w;
    Bs[0][lk + 0][lrow] = br.x; Bs[0][lk + 1][lrow] = br.y;
    Bs[0][lk + 2][lrow] = br.z; Bs[0][lk + 3][lrow] = br.w;
    __syncthreads();

    const int ntiles = K >> 3;
    int buf = 0;
    for (int t = 0; t < ntiles; ++t) {
        if (t + 1 < ntiles) {
            ar = *(const float4*)(Ap + (size_t)(t + 1) * 8);
            br = *(const float4*)(Bp + (size_t)(t + 1) * 8);
        }
#pragma unroll
        for (int k = 0; k < 8; ++k) {
            float a[8], b[8];
            *(float4*)&a[0] = *(const float4*)&As[buf][k][ty * 4];
            *(float4*)&a[4] = *(const float4*)&As[buf][k][64 + ty * 4];
            *(float4*)&b[0] = *(const float4*)&Bs[buf][k][tx * 4];
            *(float4*)&b[4] = *(const float4*)&Bs[buf][k][64 + tx * 4];
#pragma unroll
            for (int i = 0; i < 8; ++i)
#pragma unroll
                for (int j = 0; j < 8; ++j)
                    acc[i][j] = fmaf(a[i], b[j], acc[i][j]);
        }
        if (t + 1 < ntiles) {
            buf ^= 1;
            As[buf][lk + 0][lrow] = ar.x; As[buf][lk + 1][lrow] = ar.y;
            As[buf][lk + 2][lrow] = ar.z; As[buf][lk + 3][lrow] = ar.w;
            Bs[buf][lk + 0][lrow] = br.x; Bs[buf][lk + 1][lrow] = br.y;
            Bs[buf][lk + 2][lrow] = br.z; Bs[buf][lk + 3][lrow] = br.w;
            __syncthreads();
        }
    }

    // bias for this thread's 8 columns (quadrant layout)
    float bv[8];
#pragma unroll
    for (int j = 0; j < 8; ++j) {
        int cl = (j < 4) ? (tx * 4 + j) : (64 + tx * 4 + (j - 4));
        bv[j] = bias[n0 + cl];
    }

    if (mode == 0) {
#pragma unroll
        for (int i = 0; i < 8; ++i) {
            int r = m0 + ((i < 4) ? (ty * 4 + i) : (64 + ty * 4 + (i - 4)));
            float4 o0 = make_float4(acc[i][0] + bv[0], acc[i][1] + bv[1],
                                    acc[i][2] + bv[2], acc[i][3] + bv[3]);
            float4 o1 = make_float4(acc[i][4] + bv[4], acc[i][5] + bv[5],
                                    acc[i][6] + bv[6], acc[i][7] + bv[7]);
            *(float4*)&C0[(size_t)r * N + n0 + tx * 4]       = o0;
            *(float4*)&C0[(size_t)r * N + n0 + 64 + tx * 4]  = o1;
        }
    } else {
        // whole 128-col tile lies in exactly one (part, head)
        const int part = n0 >> 11;            // n0 / 2048
        const int h    = (n0 & 2047) >> 7;    // (n0 % 2048) / 128
        float* dst = (part == 0) ? C0 : (part == 1) ? C1 : C2;
#pragma unroll
        for (int i = 0; i < 8; ++i) {
            int r  = m0 + ((i < 4) ? (ty * 4 + i) : (64 + ty * 4 + (i - 4)));
            int bb = r >> 10;                 // r / 1024
            int ss = r & 1023;
            size_t base = (((size_t)(bb * HEADS + h) * SEQ) + ss) * HDIM;
            float4 o0 = make_float4(acc[i][0] + bv[0], acc[i][1] + bv[1],
                                    acc[i][2] + bv[2], acc[i][3] + bv[3]);
            float4 o1 = make_float4(acc[i][4] + bv[4], acc[i][5] + bv[5],
                                    acc[i][6] + bv[6], acc[i][7] + bv[7]);
            *(float4*)&dst[base + tx * 4]      = o0;
            *(float4*)&dst[base + 64 + tx * 4] = o1;
        }
    }
}

// ============================================================================
// Flash attention (fp32, non-causal). One block = one (b,h) x 64 q-rows.
// 256 threads (16x16). S-gemm: 4x4 per thread; PV-gemm: 4 rows x 8 cols.
// Online softmax with per-row stats replicated across the 16 tx lanes.
// ============================================================================
#define QKV_STRIDE 132
#define PS_STRIDE  68
#define FLASH_SMEM ((3 * 64 * QKV_STRIDE + 64 * PS_STRIDE) * (int)sizeof(float))

__global__ __launch_bounds__(256, 1)
void flash_attn_kernel(const float* __restrict__ Qg,
                       const float* __restrict__ Kg,
                       const float* __restrict__ Vg,
                       float* __restrict__ Cg)
{
    extern __shared__ float sm[];
    float* Qs = sm;                               // 64 x 132
    float* Ks = Qs + 64 * QKV_STRIDE;             // 64 x 132
    float* Vs = Ks + 64 * QKV_STRIDE;             // 64 x 132
    float* Ps = Vs + 64 * QKV_STRIDE;             // 64 x 68

    const int bh = blockIdx.x;                    // 0..63
    const int q0 = blockIdx.y << 6;
    const int b  = bh >> 4;
    const int h  = bh & 15;
    const float* Qp = Qg + (size_t)bh * SEQ * HDIM;
    const float* Kp = Kg + (size_t)bh * SEQ * HDIM;
    const float* Vp = Vg + (size_t)bh * SEQ * HDIM;

    const int tid = threadIdx.x;
    const int tx  = tid & 15;
    const int ty  = tid >> 4;
    const float scale = 0.088388347648318447f;    // 1/sqrt(128)

    // load Q tile (pre-scaled)
    for (int i = tid; i < 2048; i += 256) {       // 2048 float4 = 64x128
        int r = i >> 5, c = (i & 31) << 2;
        float4 v = *(const float4*)&Qp[(size_t)(q0 + r) * HDIM + c];
        v.x *= scale; v.y *= scale; v.z *= scale; v.w *= scale;
        *(float4*)&Qs[r * QKV_STRIDE + c] = v;
    }

    float O[4][8];
    float m_[4], l_[4];
#pragma unroll
    for (int i = 0; i < 4; ++i) {
        m_[i] = -INFINITY; l_[i] = 0.f;
#pragma unroll
        for (int j = 0; j < 8; ++j) O[i][j] = 0.f;
    }

    for (int kv0 = 0; kv0 < SEQ; kv0 += 64) {
        __syncthreads();   // previous iter done reading Ks/Vs/Ps (also covers Q load)
        for (int i = tid; i < 2048; i += 256) {
            int r = i >> 5, c = (i & 31) << 2;
            *(float4*)&Ks[r * QKV_STRIDE + c] =
                *(const float4*)&Kp[(size_t)(kv0 + r) * HDIM + c];
            *(float4*)&Vs[r * QKV_STRIDE + c] =
                *(const float4*)&Vp[(size_t)(kv0 + r) * HDIM + c];
        }
        __syncthreads();

        // S = (Q*scale) K^T, 4x4 per thread: rows ty*4+i, cols tx*4+j
        float sacc[4][4];
#pragma unroll
        for (int i = 0; i < 4; ++i)
#pragma unroll
            for (int j = 0; j < 4; ++j) sacc[i][j] = 0.f;

        for (int d0 = 0; d0 < HDIM; d0 += 4) {
            float4 q4[4], k4[4];
#pragma unroll
            for (int i = 0; i < 4; ++i)
                q4[i] = *(const float4*)&Qs[(ty * 4 + i) * QKV_STRIDE + d0];
#pragma unroll
            for (int j = 0; j < 4; ++j)
                k4[j] = *(const float4*)&Ks[(tx * 4 + j) * QKV_STRIDE + d0];
#pragma unroll
            for (int i = 0; i < 4; ++i)
#pragma unroll
                for (int j = 0; j < 4; ++j) {
                    sacc[i][j] = fmaf(q4[i].x, k4[j].x, sacc[i][j]);
                    sacc[i][j] = fmaf(q4[i].y, k4[j].y, sacc[i][j]);
                    sacc[i][j] = fmaf(q4[i].z, k4[j].z, sacc[i][j]);
                    sacc[i][j] = fmaf(q4[i].w, k4[j].w, sacc[i][j]);
                }
        }

        // online softmax per row (reduce across the 16 tx lanes; lanes
        // ty*16+tx sit in 16-lane shuffle segments)
#pragma unroll
        for (int i = 0; i < 4; ++i) {
            float mx = fmaxf(fmaxf(sacc[i][0], sacc[i][1]),
                             fmaxf(sacc[i][2], sacc[i][3]));
            mx = fmaxf(mx, __shfl_xor_sync(0xffffffffu, mx, 1, 16));
            mx = fmaxf(mx, __shfl_xor_sync(0xffffffffu, mx, 2, 16));
            mx = fmaxf(mx, __shfl_xor_sync(0xffffffffu, mx, 4, 16));
            mx = fmaxf(mx, __shfl_xor_sync(0xffffffffu, mx, 8, 16));
            float mnew  = fmaxf(m_[i], mx);
            float alpha = __expf(m_[i] - mnew);
            m_[i] = mnew;
            float p0 = __expf(sacc[i][0] - mnew);
            float p1 = __expf(sacc[i][1] - mnew);
            float p2 = __expf(sacc[i][2] - mnew);
            float p3 = __expf(sacc[i][3] - mnew);
            float rs = (p0 + p1) + (p2 + p3);
            rs += __shfl_xor_sync(0xffffffffu, rs, 1, 16);
            rs += __shfl_xor_sync(0xffffffffu, rs, 2, 16);
            rs += __shfl_xor_sync(0xffffffffu, rs, 4, 16);
            rs += __shfl_xor_sync(0xffffffffu, rs, 8, 16);
            l_[i] = l_[i] * alpha + rs;
#pragma unroll
            for (int j = 0; j < 8; ++j) O[i][j] *= alpha;
            float* pr = &Ps[(ty * 4 + i) * PS_STRIDE + tx * 4];
            pr[0] = p0; pr[1] = p1; pr[2] = p2; pr[3] = p3;
        }
        __syncthreads();

        // O += P V : rows ty*4+i, cols {tx*4..+3, 64+tx*4..+3}
        for (int jj = 0; jj < 64; ++jj) {
            float p[4];
#pragma unroll
            for (int i = 0; i < 4; ++i)
                p[i] = Ps[(ty * 4 + i) * PS_STRIDE + jj];
            float4 v0 = *(const float4*)&Vs[jj * QKV_STRIDE + tx * 4];
            float4 v1 = *(const float4*)&Vs[jj * QKV_STRIDE + 64 + tx * 4];
#pragma unroll
            for (int i = 0; i < 4; ++i) {
                O[i][0] = fmaf(p[i], v0.x, O[i][0]);
                O[i][1] = fmaf(p[i], v0.y, O[i][1]);
                O[i][2] = fmaf(p[i], v0.z, O[i][2]);
                O[i][3] = fmaf(p[i], v0.w, O[i][3]);
                O[i][4] = fmaf(p[i], v1.x, O[i][4]);
                O[i][5] = fmaf(p[i], v1.y, O[i][5]);
                O[i][6] = fmaf(p[i], v1.z, O[i][6]);
                O[i][7] = fmaf(p[i], v1.w, O[i][7]);
            }
        }
    }

    // normalize and write ctx in [B,S,E] layout for the out-proj GEMM
#pragma unroll
    for (int i = 0; i < 4; ++i) {
        float inv = 1.f / l_[i];
        int token = b * SEQ + q0 + ty * 4 + i;
        float* op = Cg + (size_t)token * EMB + h * HDIM;
        float4 o0 = make_float4(O[i][0] * inv, O[i][1] * inv,
                                O[i][2] * inv, O[i][3] * inv);
        float4 o1 = make_float4(O[i][4] * inv, O[i][5] * inv,
                                O[i][6] * inv, O[i][7] * inv);
        *(float4*)&op[tx * 4]      = o0;
        *(float4*)&op[64 + tx * 4] = o1;
    }
}

// ============================================================================
// Launch
// ============================================================================
extern "C" void kernel_launch(void* const* d_in, const int* in_sizes, int n_in,
                              void* d_out, int out_size)
{
    (void)in_sizes; (void)n_in; (void)out_size;
    const float* x     = (const float*)d_in[0];  // query [B,S,E]
    const float* w_in  = (const float*)d_in[1];  // [3E, E]
    const float* b_in  = (const float*)d_in[2];  // [3E]
    const float* w_out = (const float*)d_in[3];  // [E, E]
    const float* b_out = (const float*)d_in[4];  // [E]
    float* out = (float*)d_out;                  // [B,S,E]

    float *qp, *kp, *vp, *cp;
    cudaGetSymbolAddress((void**)&qp, g_q);
    cudaGetSymbolAddress((void**)&kp, g_k);
    cudaGetSymbolAddress((void**)&vp, g_v);
    cudaGetSymbolAddress((void**)&cp, g_ctx);

    cudaFuncSetAttribute(flash_attn_kernel,
                         cudaFuncAttributeMaxDynamicSharedMemorySize, FLASH_SMEM);

    // 1) fused QKV projection, scattered into [B,H,S,D] per head
    dim3 g1(QKVN / 128, MTOK / 128);
    sgemm_nt_kernel<<<g1, 256>>>(x, w_in, b_in, qp, kp, vp,
                                 MTOK, QKVN, EMB, 1);

    // 2) flash attention -> ctx [B,S,E]
    dim3 g2(BATCH * HEADS, SEQ / 64);
    flash_attn_kernel<<<g2, 256, FLASH_SMEM>>>(qp, kp, vp, cp);

    // 3) output projection
    dim3 g3(EMB / 128, MTOK / 128);
    sgemm_nt_kernel<<<g3, 256>>>(cp, w_out, b_out, out, nullptr, nullptr,
                                 MTOK, EMB, EMB, 0);
}

// round 4
// speedup vs baseline: 1.4505x; 1.4493x over previous
#include <cuda_runtime.h>
#include <cuda_bf16.h>
#include <math.h>
#include <stdint.h>

#define BATCH 4
#define SEQ   1024
#define EMB   2048
#define HEADS 16
#define HDIM  128
#define MTOK  4096
#define QKVN  6144

// Scratch (device globals: no cudaMalloc allowed)
__device__ float g_q[8388608];
__device__ float g_k[8388608];
__device__ float g_v[8388608];
__device__ float g_ctx[8388608];
__device__ __nv_bfloat16 g_x_hi[8388608];
__device__ __nv_bfloat16 g_x_lo[8388608];
__device__ __nv_bfloat16 g_wi_hi[12582912];
__device__ __nv_bfloat16 g_wi_lo[12582912];
__device__ __nv_bfloat16 g_wo_hi[4194304];
__device__ __nv_bfloat16 g_wo_lo[4194304];
__device__ __nv_bfloat16 g_ctx_hi[8388608];
__device__ __nv_bfloat16 g_ctx_lo[8388608];

// ======================= helpers ============================================
__device__ __forceinline__ uint32_t smem_u32(const void* p) {
    uint32_t a;
    asm("{ .reg .u64 t; cvta.to.shared.u64 t, %1; cvt.u32.u64 %0, t; }"
        : "=r"(a) : "l"(p));
    return a;
}
__device__ __forceinline__ void cp16(uint32_t dst, const void* src) {
    asm volatile("cp.async.cg.shared.global [%0], [%1], 16;"
                 :: "r"(dst), "l"(src) : "memory");
}
__device__ __forceinline__ void cp_commit() {
    asm volatile("cp.async.commit_group;" ::: "memory");
}
__device__ __forceinline__ void cp_wait3() {
    asm volatile("cp.async.wait_group 3;" ::: "memory");
}
__device__ __forceinline__ void ldsm_x4(uint32_t (&r)[4], uint32_t a) {
    asm volatile("ldmatrix.sync.aligned.m8n8.x4.shared.b16 {%0,%1,%2,%3}, [%4];"
                 : "=r"(r[0]), "=r"(r[1]), "=r"(r[2]), "=r"(r[3]) : "r"(a));
}
__device__ __forceinline__ void ldsm_x2(uint32_t (&r)[2], uint32_t a) {
    asm volatile("ldmatrix.sync.aligned.m8n8.x2.shared.b16 {%0,%1}, [%2];"
                 : "=r"(r[0]), "=r"(r[1]) : "r"(a));
}
__device__ __forceinline__ void mma_bf16(float (&d)[4], const uint32_t (&a)[4],
                                         const uint32_t (&b)[2]) {
    asm volatile(
        "mma.sync.aligned.m16n8k16.row.col.f32.bf16.bf16.f32 "
        "{%0,%1,%2,%3}, {%4,%5,%6,%7}, {%8,%9}, {%0,%1,%2,%3};"
        : "+f"(d[0]), "+f"(d[1]), "+f"(d[2]), "+f"(d[3])
        : "r"(a[0]), "r"(a[1]), "r"(a[2]), "r"(a[3]), "r"(b[0]), "r"(b[1]));
}

// ======================= bf16 hi/lo split ===================================
__global__ void split_bf16_kernel(const float4* __restrict__ in,
                                  __nv_bfloat162* __restrict__ hi,
                                  __nv_bfloat162* __restrict__ lo, int n4)
{
    int i = blockIdx.x * blockDim.x + threadIdx.x;
    if (i >= n4) return;
    float4 v = in[i];
    __nv_bfloat16 h0 = __float2bfloat16_rn(v.x);
    __nv_bfloat16 h1 = __float2bfloat16_rn(v.y);
    __nv_bfloat16 h2 = __float2bfloat16_rn(v.z);
    __nv_bfloat16 h3 = __float2bfloat16_rn(v.w);
    __nv_bfloat16 l0 = __float2bfloat16_rn(v.x - __bfloat162float(h0));
    __nv_bfloat16 l1 = __float2bfloat16_rn(v.y - __bfloat162float(h1));
    __nv_bfloat16 l2 = __float2bfloat16_rn(v.z - __bfloat162float(h2));
    __nv_bfloat16 l3 = __float2bfloat16_rn(v.w - __bfloat162float(h3));
    hi[2 * i]     = __nv_bfloat162(h0, h1);
    hi[2 * i + 1] = __nv_bfloat162(h2, h3);
    lo[2 * i]     = __nv_bfloat162(l0, l1);
    lo[2 * i + 1] = __nv_bfloat162(l2, l3);
}

// ======================= bf16x3 mma.sync GEMM-NT ============================
// C[m,n] = sum_k A[m,k]*B[n,k] + bias[n]
// 128x128 CTA tile, BK=32, 4-stage cp.async pipeline, 8 warps (64x32 each).
// mode 0: C0 row-major [M,N]; mode 1: scatter QKV into [B,H,S,D].
#define SROW    80                       // bytes per smem row (32 bf16 + pad)
#define MATB    (128 * SROW)             // 10240 B per matrix tile
#define STAGEB  (4 * MATB)               // 40960 B (Ahi,Alo,Bhi,Blo)
#define STAGES  4
#define GEMM_SMEM (STAGES * STAGEB)      // 163840 B

__global__ __launch_bounds__(256, 1)
void mma_gemm_kernel(const __nv_bfloat16* __restrict__ Ahi,
                     const __nv_bfloat16* __restrict__ Alo,
                     const __nv_bfloat16* __restrict__ Bhi,
                     const __nv_bfloat16* __restrict__ Blo,
                     const float* __restrict__ bias,
                     float* __restrict__ C0, float* __restrict__ C1,
                     float* __restrict__ C2,
                     int N, int K, int mode)
{
    extern __shared__ __align__(128) char smem[];
    const uint32_t sb = smem_u32(smem);
    const int tid  = threadIdx.x;
    const int lane = tid & 31;
    const int warp = tid >> 5;
    const int m0 = blockIdx.y << 7;
    const int n0 = blockIdx.x << 7;
    const int wm = (warp >> 2) << 6;     // warp row offset (0/64)
    const int wn = (warp & 3) << 5;      // warp col offset (0/32/64/96)
    const int KT = K >> 5;

    const char* gsrc0 = (const char*)(Ahi + (size_t)m0 * K);
    const char* gsrc1 = (const char*)(Alo + (size_t)m0 * K);
    const char* gsrc2 = (const char*)(Bhi + (size_t)n0 * K);
    const char* gsrc3 = (const char*)(Blo + (size_t)n0 * K);
    const size_t grs = (size_t)K * 2;    // global row stride bytes

    const int lr  = tid >> 2;            // load rows: lr and lr+64
    const int lch = (tid & 3) << 4;      // 16B chunk within row

#define LOAD_STAGE(t, slot) do {                                             \
    const uint32_t base_ = sb + (slot) * STAGEB;                             \
    const size_t koff_ = (size_t)(t) * 64;                                   \
    const char* gs_[4] = { gsrc0, gsrc1, gsrc2, gsrc3 };                     \
    _Pragma("unroll")                                                        \
    for (int mx_ = 0; mx_ < 4; ++mx_) {                                      \
        uint32_t mb_ = base_ + mx_ * MATB;                                   \
        cp16(mb_ + lr * SROW + lch,                                          \
             gs_[mx_] + (size_t)lr * grs + koff_ + lch);                     \
        cp16(mb_ + (lr + 64) * SROW + lch,                                   \
             gs_[mx_] + (size_t)(lr + 64) * grs + koff_ + lch);              \
    }                                                                        \
} while (0)

    float acc[4][4][4];
#pragma unroll
    for (int i = 0; i < 4; ++i)
#pragma unroll
        for (int j = 0; j < 4; ++j)
#pragma unroll
            for (int r = 0; r < 4; ++r) acc[i][j][r] = 0.f;

    // ldmatrix per-lane address components
    const uint32_t arow = (uint32_t)((lane & 15) * SROW + (lane >> 4) * 16);
    const uint32_t brow = (uint32_t)((lane & 7) * SROW + ((lane >> 3) & 1) * 16);

    // prologue: stages 0..2
    LOAD_STAGE(0, 0); cp_commit();
    LOAD_STAGE(1, 1); cp_commit();
    LOAD_STAGE(2, 2); cp_commit();

    for (int t = 0; t < KT; ++t) {
        if (t + 3 < KT) LOAD_STAGE(t + 3, (t + 3) & 3);
        cp_commit();
        cp_wait3();
        __syncthreads();

        const uint32_t slot = sb + (t & 3) * STAGEB;
#pragma unroll
        for (int s = 0; s < 2; ++s) {
            const uint32_t ks = s * 32;
            uint32_t aH[4][4], aL[4][4], bH[4][2], bL[4][2];
#pragma unroll
            for (int i = 0; i < 4; ++i) {
                uint32_t ad = slot + (wm + i * 16) * SROW + ks + arow;
                ldsm_x4(aH[i], ad);
                ldsm_x4(aL[i], ad + MATB);
            }
#pragma unroll
            for (int j = 0; j < 4; ++j) {
                uint32_t bd = slot + 2 * MATB + (wn + j * 8) * SROW + ks + brow;
                ldsm_x2(bH[j], bd);
                ldsm_x2(bL[j], bd + MATB);
            }
#pragma unroll
            for (int i = 0; i < 4; ++i)
#pragma unroll
                for (int j = 0; j < 4; ++j) {
                    mma_bf16(acc[i][j], aH[i], bH[j]);
                    mma_bf16(acc[i][j], aH[i], bL[j]);
                    mma_bf16(acc[i][j], aL[i], bH[j]);
                }
        }
        __syncthreads();
    }

    // ---------------- epilogue ----------------
    const int r0 = lane >> 2;            // fragment row within 16
    const int c0 = (lane & 3) << 1;      // fragment col within 8

    // per-j bias (cols independent of i)
    float bj[4][2];
#pragma unroll
    for (int j = 0; j < 4; ++j) {
        int nc = n0 + wn + j * 8 + c0;
        bj[j][0] = __ldg(&bias[nc]);
        bj[j][1] = __ldg(&bias[nc + 1]);
    }

    if (mode == 0) {
#pragma unroll
        for (int i = 0; i < 4; ++i) {
            int mr = m0 + wm + i * 16 + r0;
#pragma unroll
            for (int j = 0; j < 4; ++j) {
                int nc = n0 + wn + j * 8 + c0;
                float2 v0 = make_float2(acc[i][j][0] + bj[j][0],
                                        acc[i][j][1] + bj[j][1]);
                float2 v1 = make_float2(acc[i][j][2] + bj[j][0],
                                        acc[i][j][3] + bj[j][1]);
                *(float2*)&C0[(size_t)mr * N + nc]       = v0;
                *(float2*)&C0[(size_t)(mr + 8) * N + nc] = v1;
            }
        }
    } else {
        // whole CTA column tile lies in one (part, head)
        const int part = n0 >> 11;
        const int hh   = (n0 >> 7) & 15;
        float* base = (part == 0) ? C0 : (part == 1) ? C1 : C2;
#pragma unroll
        for (int i = 0; i < 4; ++i) {
            int mr = m0 + wm + i * 16 + r0;
            int bb = mr >> 10, ss = mr & 1023;
            size_t rb0 = (((size_t)(bb * HEADS + hh) * SEQ) + ss) << 7;
            int mr8 = mr + 8;
            int bb8 = mr8 >> 10, ss8 = mr8 & 1023;
            size_t rb1 = (((size_t)(bb8 * HEADS + hh) * SEQ) + ss8) << 7;
#pragma unroll
            for (int j = 0; j < 4; ++j) {
                int d = wn + j * 8 + c0;           // within-head dim
                float2 v0 = make_float2(acc[i][j][0] + bj[j][0],
                                        acc[i][j][1] + bj[j][1]);
                float2 v1 = make_float2(acc[i][j][2] + bj[j][0],
                                        acc[i][j][3] + bj[j][1]);
                *(float2*)&base[rb0 + d] = v0;
                *(float2*)&base[rb1 + d] = v1;
            }
        }
    }
#undef LOAD_STAGE
}

// ======================= Flash attention (unchanged, passing) ===============
#define QKV_STRIDE 132
#define PS_STRIDE  68
#define FLASH_SMEM ((3 * 64 * QKV_STRIDE + 64 * PS_STRIDE) * (int)sizeof(float))

__global__ __launch_bounds__(256, 1)
void flash_attn_kernel(const float* __restrict__ Qg,
                       const float* __restrict__ Kg,
                       const float* __restrict__ Vg,
                       float* __restrict__ Cg)
{
    extern __shared__ float sm[];
    float* Qs = sm;
    float* Ks = Qs + 64 * QKV_STRIDE;
    float* Vs = Ks + 64 * QKV_STRIDE;
    float* Ps = Vs + 64 * QKV_STRIDE;

    const int bh = blockIdx.x;
    const int q0 = blockIdx.y << 6;
    const int b  = bh >> 4;
    const int h  = bh & 15;
    const float* Qp = Qg + (size_t)bh * SEQ * HDIM;
    const float* Kp = Kg + (size_t)bh * SEQ * HDIM;
    const float* Vp = Vg + (size_t)bh * SEQ * HDIM;

    const int tid = threadIdx.x;
    const int tx  = tid & 15;
    const int ty  = tid >> 4;
    const float scale = 0.088388347648318447f;

    for (int i = tid; i < 2048; i += 256) {
        int r = i >> 5, c = (i & 31) << 2;
        float4 v = *(const float4*)&Qp[(size_t)(q0 + r) * HDIM + c];
        v.x *= scale; v.y *= scale; v.z *= scale; v.w *= scale;
        *(float4*)&Qs[r * QKV_STRIDE + c] = v;
    }

    float O[4][8];
    float m_[4], l_[4];
#pragma unroll
    for (int i = 0; i < 4; ++i) {
        m_[i] = -INFINITY; l_[i] = 0.f;
#pragma unroll
        for (int j = 0; j < 8; ++j) O[i][j] = 0.f;
    }

    for (int kv0 = 0; kv0 < SEQ; kv0 += 64) {
        __syncthreads();
        for (int i = tid; i < 2048; i += 256) {
            int r = i >> 5, c = (i & 31) << 2;
            *(float4*)&Ks[r * QKV_STRIDE + c] =
                *(const float4*)&Kp[(size_t)(kv0 + r) * HDIM + c];
            *(float4*)&Vs[r * QKV_STRIDE + c] =
                *(const float4*)&Vp[(size_t)(kv0 + r) * HDIM + c];
        }
        __syncthreads();

        float sacc[4][4];
#pragma unroll
        for (int i = 0; i < 4; ++i)
#pragma unroll
            for (int j = 0; j < 4; ++j) sacc[i][j] = 0.f;

        for (int d0 = 0; d0 < HDIM; d0 += 4) {
            float4 q4[4], k4[4];
#pragma unroll
            for (int i = 0; i < 4; ++i)
                q4[i] = *(const float4*)&Qs[(ty * 4 + i) * QKV_STRIDE + d0];
#pragma unroll
            for (int j = 0; j < 4; ++j)
                k4[j] = *(const float4*)&Ks[(tx * 4 + j) * QKV_STRIDE + d0];
#pragma unroll
            for (int i = 0; i < 4; ++i)
#pragma unroll
                for (int j = 0; j < 4; ++j) {
                    sacc[i][j] = fmaf(q4[i].x, k4[j].x, sacc[i][j]);
                    sacc[i][j] = fmaf(q4[i].y, k4[j].y, sacc[i][j]);
                    sacc[i][j] = fmaf(q4[i].z, k4[j].z, sacc[i][j]);
                    sacc[i][j] = fmaf(q4[i].w, k4[j].w, sacc[i][j]);
                }
        }

#pragma unroll
        for (int i = 0; i < 4; ++i) {
            float mx = fmaxf(fmaxf(sacc[i][0], sacc[i][1]),
                             fmaxf(sacc[i][2], sacc[i][3]));
            mx = fmaxf(mx, __shfl_xor_sync(0xffffffffu, mx, 1, 16));
            mx = fmaxf(mx, __shfl_xor_sync(0xffffffffu, mx, 2, 16));
            mx = fmaxf(mx, __shfl_xor_sync(0xffffffffu, mx, 4, 16));
            mx = fmaxf(mx, __shfl_xor_sync(0xffffffffu, mx, 8, 16));
            float mnew  = fmaxf(m_[i], mx);
            float alpha = __expf(m_[i] - mnew);
            m_[i] = mnew;
            float p0 = __expf(sacc[i][0] - mnew);
            float p1 = __expf(sacc[i][1] - mnew);
            float p2 = __expf(sacc[i][2] - mnew);
            float p3 = __expf(sacc[i][3] - mnew);
            float rs = (p0 + p1) + (p2 + p3);
            rs += __shfl_xor_sync(0xffffffffu, rs, 1, 16);
            rs += __shfl_xor_sync(0xffffffffu, rs, 2, 16);
            rs += __shfl_xor_sync(0xffffffffu, rs, 4, 16);
            rs += __shfl_xor_sync(0xffffffffu, rs, 8, 16);
            l_[i] = l_[i] * alpha + rs;
#pragma unroll
            for (int j = 0; j < 8; ++j) O[i][j] *= alpha;
            float* pr = &Ps[(ty * 4 + i) * PS_STRIDE + tx * 4];
            pr[0] = p0; pr[1] = p1; pr[2] = p2; pr[3] = p3;
        }
        __syncthreads();

        for (int jj = 0; jj < 64; ++jj) {
            float p[4];
#pragma unroll
            for (int i = 0; i < 4; ++i)
                p[i] = Ps[(ty * 4 + i) * PS_STRIDE + jj];
            float4 v0 = *(const float4*)&Vs[jj * QKV_STRIDE + tx * 4];
            float4 v1 = *(const float4*)&Vs[jj * QKV_STRIDE + 64 + tx * 4];
#pragma unroll
            for (int i = 0; i < 4; ++i) {
                O[i][0] = fmaf(p[i], v0.x, O[i][0]);
                O[i][1] = fmaf(p[i], v0.y, O[i][1]);
                O[i][2] = fmaf(p[i], v0.z, O[i][2]);
                O[i][3] = fmaf(p[i], v0.w, O[i][3]);
                O[i][4] = fmaf(p[i], v1.x, O[i][4]);
                O[i][5] = fmaf(p[i], v1.y, O[i][5]);
                O[i][6] = fmaf(p[i], v1.z, O[i][6]);
                O[i][7] = fmaf(p[i], v1.w, O[i][7]);
            }
        }
    }

#pragma unroll
    for (int i = 0; i < 4; ++i) {
        float inv = 1.f / l_[i];
        int token = b * SEQ + q0 + ty * 4 + i;
        float* op = Cg + (size_t)token * EMB + h * HDIM;
        float4 o0 = make_float4(O[i][0] * inv, O[i][1] * inv,
                                O[i][2] * inv, O[i][3] * inv);
        float4 o1 = make_float4(O[i][4] * inv, O[i][5] * inv,
                                O[i][6] * inv, O[i][7] * inv);
        *(float4*)&op[tx * 4]      = o0;
        *(float4*)&op[64 + tx * 4] = o1;
    }
}

// ======================= Launch =============================================
extern "C" void kernel_launch(void* const* d_in, const int* in_sizes, int n_in,
                              void* d_out, int out_size)
{
    (void)in_sizes; (void)n_in; (void)out_size;
    const float* x     = (const float*)d_in[0];
    const float* w_in  = (const float*)d_in[1];
    const float* b_in  = (const float*)d_in[2];
    const float* w_out = (const float*)d_in[3];
    const float* b_out = (const float*)d_in[4];
    float* out = (float*)d_out;

    float *qp, *kp, *vp, *cp;
    __nv_bfloat16 *xh, *xl, *wih, *wil, *woh, *wol, *chp, *clp;
    cudaGetSymbolAddress((void**)&qp,  g_q);
    cudaGetSymbolAddress((void**)&kp,  g_k);
    cudaGetSymbolAddress((void**)&vp,  g_v);
    cudaGetSymbolAddress((void**)&cp,  g_ctx);
    cudaGetSymbolAddress((void**)&xh,  g_x_hi);
    cudaGetSymbolAddress((void**)&xl,  g_x_lo);
    cudaGetSymbolAddress((void**)&wih, g_wi_hi);
    cudaGetSymbolAddress((void**)&wil, g_wi_lo);
    cudaGetSymbolAddress((void**)&woh, g_wo_hi);
    cudaGetSymbolAddress((void**)&wol, g_wo_lo);
    cudaGetSymbolAddress((void**)&chp, g_ctx_hi);
    cudaGetSymbolAddress((void**)&clp, g_ctx_lo);

    cudaFuncSetAttribute(flash_attn_kernel,
                         cudaFuncAttributeMaxDynamicSharedMemorySize, FLASH_SMEM);
    cudaFuncSetAttribute(mma_gemm_kernel,
                         cudaFuncAttributeMaxDynamicSharedMemorySize, GEMM_SMEM);

    // bf16 hi/lo splits
    {
        int n4 = MTOK * EMB / 4;
        split_bf16_kernel<<<n4 / 256, 256>>>((const float4*)x,
            (__nv_bfloat162*)xh, (__nv_bfloat162*)xl, n4);
    }
    {
        int n4 = QKVN * EMB / 4;
        split_bf16_kernel<<<n4 / 256, 256>>>((const float4*)w_in,
            (__nv_bfloat162*)wih, (__nv_bfloat162*)wil, n4);
    }
    {
        int n4 = EMB * EMB / 4;
        split_bf16_kernel<<<n4 / 256, 256>>>((const float4*)w_out,
            (__nv_bfloat162*)woh, (__nv_bfloat162*)wol, n4);
    }

    // 1) QKV projection -> [B,H,S,D] scatter
    {
        dim3 g(QKVN / 128, MTOK / 128);
        mma_gemm_kernel<<<g, 256, GEMM_SMEM>>>(xh, xl, wih, wil, b_in,
                                               qp, kp, vp, QKVN, EMB, 1);
    }

    // 2) flash attention -> ctx [B,S,E]
    {
        dim3 g(BATCH * HEADS, SEQ / 64);
        flash_attn_kernel<<<g, 256, FLASH_SMEM>>>(qp, kp, vp, cp);
    }

    // split ctx for out-proj
    {
        int n4 = MTOK * EMB / 4;
        split_bf16_kernel<<<n4 / 256, 256>>>((const float4*)cp,
            (__nv_bfloat162*)chp, (__nv_bfloat162*)clp, n4);
    }

    // 3) output projection
    {
        dim3 g(EMB / 128, MTOK / 128);
        mma_gemm_kernel<<<g, 256, GEMM_SMEM>>>(chp, clp, woh, wol, b_out,
                                               out, nullptr, nullptr,
                                               EMB, EMB, 0);
    }
}

// round 5
// speedup vs baseline: 2.5170x; 1.7353x over previous
#include <cuda_runtime.h>
#include <cuda_bf16.h>
#include <math.h>
#include <stdint.h>

#define BATCH 4
#define SEQ   1024
#define EMB   2048
#define HEADS 16
#define HDIM  128
#define MTOK  4096
#define QKVN  6144

// Scratch (device globals: no cudaMalloc allowed)
__device__ __nv_bfloat16 g_qh[8388608];
__device__ __nv_bfloat16 g_ql[8388608];
__device__ __nv_bfloat16 g_kh[8388608];
__device__ __nv_bfloat16 g_kl[8388608];
__device__ __nv_bfloat16 g_vh[8388608];
__device__ __nv_bfloat16 g_vl[8388608];
__device__ __nv_bfloat16 g_ch[8388608];
__device__ __nv_bfloat16 g_cl[8388608];
__device__ __nv_bfloat16 g_x_hi[8388608];
__device__ __nv_bfloat16 g_x_lo[8388608];
__device__ __nv_bfloat16 g_wi_hi[12582912];
__device__ __nv_bfloat16 g_wi_lo[12582912];
__device__ __nv_bfloat16 g_wo_hi[4194304];
__device__ __nv_bfloat16 g_wo_lo[4194304];

// ======================= helpers ============================================
__device__ __forceinline__ uint32_t smem_u32(const void* p) {
    uint32_t a;
    asm("{ .reg .u64 t; cvta.to.shared.u64 t, %1; cvt.u32.u64 %0, t; }"
        : "=r"(a) : "l"(p));
    return a;
}
__device__ __forceinline__ void cp16(uint32_t dst, const void* src) {
    asm volatile("cp.async.cg.shared.global [%0], [%1], 16;"
                 :: "r"(dst), "l"(src) : "memory");
}
__device__ __forceinline__ void cp_commit() {
    asm volatile("cp.async.commit_group;" ::: "memory");
}
__device__ __forceinline__ void cp_wait3() {
    asm volatile("cp.async.wait_group 3;" ::: "memory");
}
__device__ __forceinline__ void cp_wait0() {
    asm volatile("cp.async.wait_group 0;" ::: "memory");
}
__device__ __forceinline__ void ldsm_x4(uint32_t (&r)[4], uint32_t a) {
    asm volatile("ldmatrix.sync.aligned.m8n8.x4.shared.b16 {%0,%1,%2,%3}, [%4];"
                 : "=r"(r[0]), "=r"(r[1]), "=r"(r[2]), "=r"(r[3]) : "r"(a));
}
__device__ __forceinline__ void ldsm_x4t(uint32_t (&r)[4], uint32_t a) {
    asm volatile("ldmatrix.sync.aligned.m8n8.x4.trans.shared.b16 {%0,%1,%2,%3}, [%4];"
                 : "=r"(r[0]), "=r"(r[1]), "=r"(r[2]), "=r"(r[3]) : "r"(a));
}
__device__ __forceinline__ void ldsm_x2(uint32_t (&r)[2], uint32_t a) {
    asm volatile("ldmatrix.sync.aligned.m8n8.x2.shared.b16 {%0,%1}, [%2];"
                 : "=r"(r[0]), "=r"(r[1]) : "r"(a));
}
__device__ __forceinline__ void mma_bf16(float (&d)[4], const uint32_t (&a)[4],
                                         const uint32_t (&b)[2]) {
    asm volatile(
        "mma.sync.aligned.m16n8k16.row.col.f32.bf16.bf16.f32 "
        "{%0,%1,%2,%3}, {%4,%5,%6,%7}, {%8,%9}, {%0,%1,%2,%3};"
        : "+f"(d[0]), "+f"(d[1]), "+f"(d[2]), "+f"(d[3])
        : "r"(a[0]), "r"(a[1]), "r"(a[2]), "r"(a[3]), "r"(b[0]), "r"(b[1]));
}
__device__ __forceinline__ void mma2(float (&d)[4], const uint32_t (&a)[4],
                                     uint32_t b0, uint32_t b1) {
    asm volatile(
        "mma.sync.aligned.m16n8k16.row.col.f32.bf16.bf16.f32 "
        "{%0,%1,%2,%3}, {%4,%5,%6,%7}, {%8,%9}, {%0,%1,%2,%3};"
        : "+f"(d[0]), "+f"(d[1]), "+f"(d[2]), "+f"(d[3])
        : "r"(a[0]), "r"(a[1]), "r"(a[2]), "r"(a[3]), "r"(b0), "r"(b1));
}
// pack (x,y) -> bf16x2 hi, residual bf16x2 lo (x in low half = lower column)
__device__ __forceinline__ uint32_t packpair(float x, float y, uint32_t& lo) {
    __nv_bfloat16 hx = __float2bfloat16_rn(x);
    __nv_bfloat16 hy = __float2bfloat16_rn(y);
    __nv_bfloat162 h(hx, hy);
    __nv_bfloat162 l(__float2bfloat16_rn(x - __bfloat162float(hx)),
                     __float2bfloat16_rn(y - __bfloat162float(hy)));
    lo = *(uint32_t*)&l;
    return *(uint32_t*)&h;
}

// ======================= bf16 hi/lo split ===================================
__global__ void split_bf16_kernel(const float4* __restrict__ in,
                                  __nv_bfloat162* __restrict__ hi,
                                  __nv_bfloat162* __restrict__ lo, int n4)
{
    int i = blockIdx.x * blockDim.x + threadIdx.x;
    if (i >= n4) return;
    float4 v = in[i];
    __nv_bfloat16 h0 = __float2bfloat16_rn(v.x);
    __nv_bfloat16 h1 = __float2bfloat16_rn(v.y);
    __nv_bfloat16 h2 = __float2bfloat16_rn(v.z);
    __nv_bfloat16 h3 = __float2bfloat16_rn(v.w);
    __nv_bfloat16 l0 = __float2bfloat16_rn(v.x - __bfloat162float(h0));
    __nv_bfloat16 l1 = __float2bfloat16_rn(v.y - __bfloat162float(h1));
    __nv_bfloat16 l2 = __float2bfloat16_rn(v.z - __bfloat162float(h2));
    __nv_bfloat16 l3 = __float2bfloat16_rn(v.w - __bfloat162float(h3));
    hi[2 * i]     = __nv_bfloat162(h0, h1);
    hi[2 * i + 1] = __nv_bfloat162(h2, h3);
    lo[2 * i]     = __nv_bfloat162(l0, l1);
    lo[2 * i + 1] = __nv_bfloat162(l2, l3);
}

// ======================= bf16x3 mma.sync GEMM-NT ============================
// mode 0: C0[m*N+n] fp32 (+bias). mode 1: QKV -> bf16 hi/lo split scatter into
// [B,H,S,D] (q pre-scaled by 1/sqrt(d)).
#define SROW    80
#define MATB    (128 * SROW)
#define STAGEB  (4 * MATB)
#define STAGES  4
#define GEMM_SMEM (STAGES * STAGEB)

__global__ __launch_bounds__(256, 1)
void mma_gemm_kernel(const __nv_bfloat16* __restrict__ Ahi,
                     const __nv_bfloat16* __restrict__ Alo,
                     const __nv_bfloat16* __restrict__ Bhi,
                     const __nv_bfloat16* __restrict__ Blo,
                     const float* __restrict__ bias,
                     float* __restrict__ C0,
                     __nv_bfloat16* __restrict__ QHo, __nv_bfloat16* __restrict__ QLo,
                     __nv_bfloat16* __restrict__ KHo, __nv_bfloat16* __restrict__ KLo,
                     __nv_bfloat16* __restrict__ VHo, __nv_bfloat16* __restrict__ VLo,
                     int N, int K, int mode)
{
    extern __shared__ __align__(128) char smem[];
    const uint32_t sb = smem_u32(smem);
    const int tid  = threadIdx.x;
    const int lane = tid & 31;
    const int warp = tid >> 5;
    const int m0 = blockIdx.y << 7;
    const int n0 = blockIdx.x << 7;
    const int wm = (warp >> 2) << 6;
    const int wn = (warp & 3) << 5;
    const int KT = K >> 5;

    const char* gsrc0 = (const char*)(Ahi + (size_t)m0 * K);
    const char* gsrc1 = (const char*)(Alo + (size_t)m0 * K);
    const char* gsrc2 = (const char*)(Bhi + (size_t)n0 * K);
    const char* gsrc3 = (const char*)(Blo + (size_t)n0 * K);
    const size_t grs = (size_t)K * 2;

    const int lr  = tid >> 2;
    const int lch = (tid & 3) << 4;

#define LOAD_STAGE(t, slot) do {                                             \
    const uint32_t base_ = sb + (slot) * STAGEB;                             \
    const size_t koff_ = (size_t)(t) * 64;                                   \
    const char* gs_[4] = { gsrc0, gsrc1, gsrc2, gsrc3 };                     \
    _Pragma("unroll")                                                        \
    for (int mx_ = 0; mx_ < 4; ++mx_) {                                      \
        uint32_t mb_ = base_ + mx_ * MATB;                                   \
        cp16(mb_ + lr * SROW + lch,                                          \
             gs_[mx_] + (size_t)lr * grs + koff_ + lch);                     \
        cp16(mb_ + (lr + 64) * SROW + lch,                                   \
             gs_[mx_] + (size_t)(lr + 64) * grs + koff_ + lch);              \
    }                                                                        \
} while (0)

    float acc[4][4][4];
#pragma unroll
    for (int i = 0; i < 4; ++i)
#pragma unroll
        for (int j = 0; j < 4; ++j)
#pragma unroll
            for (int r = 0; r < 4; ++r) acc[i][j][r] = 0.f;

    const uint32_t arow = (uint32_t)((lane & 15) * SROW + (lane >> 4) * 16);
    const uint32_t brow = (uint32_t)((lane & 7) * SROW + ((lane >> 3) & 1) * 16);

    LOAD_STAGE(0, 0); cp_commit();
    LOAD_STAGE(1, 1); cp_commit();
    LOAD_STAGE(2, 2); cp_commit();

    for (int t = 0; t < KT; ++t) {
        if (t + 3 < KT) LOAD_STAGE(t + 3, (t + 3) & 3);
        cp_commit();
        cp_wait3();
        __syncthreads();

        const uint32_t slot = sb + (t & 3) * STAGEB;
#pragma unroll
        for (int s = 0; s < 2; ++s) {
            const uint32_t ks = s * 32;
            uint32_t aH[4][4], aL[4][4], bH[4][2], bL[4][2];
#pragma unroll
            for (int i = 0; i < 4; ++i) {
                uint32_t ad = slot + (wm + i * 16) * SROW + ks + arow;
                ldsm_x4(aH[i], ad);
                ldsm_x4(aL[i], ad + MATB);
            }
#pragma unroll
            for (int j = 0; j < 4; ++j) {
                uint32_t bd = slot + 2 * MATB + (wn + j * 8) * SROW + ks + brow;
                ldsm_x2(bH[j], bd);
                ldsm_x2(bL[j], bd + MATB);
            }
#pragma unroll
            for (int i = 0; i < 4; ++i)
#pragma unroll
                for (int j = 0; j < 4; ++j) {
                    mma_bf16(acc[i][j], aH[i], bH[j]);
                    mma_bf16(acc[i][j], aH[i], bL[j]);
                    mma_bf16(acc[i][j], aL[i], bH[j]);
                }
        }
        __syncthreads();
    }

    const int r0 = lane >> 2;
    const int c0 = (lane & 3) << 1;
    float bj[4][2];
#pragma unroll
    for (int j = 0; j < 4; ++j) {
        int nc = n0 + wn + j * 8 + c0;
        bj[j][0] = __ldg(&bias[nc]);
        bj[j][1] = __ldg(&bias[nc + 1]);
    }

    if (mode == 0) {
#pragma unroll
        for (int i = 0; i < 4; ++i) {
            int mr = m0 + wm + i * 16 + r0;
#pragma unroll
            for (int j = 0; j < 4; ++j) {
                int nc = n0 + wn + j * 8 + c0;
                float2 v0 = make_float2(acc[i][j][0] + bj[j][0],
                                        acc[i][j][1] + bj[j][1]);
                float2 v1 = make_float2(acc[i][j][2] + bj[j][0],
                                        acc[i][j][3] + bj[j][1]);
                *(float2*)&C0[(size_t)mr * N + nc]       = v0;
                *(float2*)&C0[(size_t)(mr + 8) * N + nc] = v1;
            }
        }
    } else {
        const int part = n0 >> 11;
        const int hh   = (n0 >> 7) & 15;
        __nv_bfloat16 *hp, *lp;
        float scl = 1.f;
        if (part == 0) { hp = QHo; lp = QLo; scl = 0.088388347648318447f; }
        else if (part == 1) { hp = KHo; lp = KLo; }
        else { hp = VHo; lp = VLo; }
#pragma unroll
        for (int i = 0; i < 4; ++i) {
            int mr = m0 + wm + i * 16 + r0;
            int bb = mr >> 10, ss = mr & 1023;
            size_t rb0 = (((size_t)(bb * HEADS + hh) * SEQ) + ss) << 7;
            int mr8 = mr + 8;
            int bb8 = mr8 >> 10, ss8 = mr8 & 1023;
            size_t rb1 = (((size_t)(bb8 * HEADS + hh) * SEQ) + ss8) << 7;
#pragma unroll
            for (int j = 0; j < 4; ++j) {
                int d = wn + j * 8 + c0;
                uint32_t lo_;
                uint32_t hi_ = packpair((acc[i][j][0] + bj[j][0]) * scl,
                                        (acc[i][j][1] + bj[j][1]) * scl, lo_);
                *(uint32_t*)(hp + rb0 + d) = hi_;
                *(uint32_t*)(lp + rb0 + d) = lo_;
                hi_ = packpair((acc[i][j][2] + bj[j][0]) * scl,
                               (acc[i][j][3] + bj[j][1]) * scl, lo_);
                *(uint32_t*)(hp + rb1 + d) = hi_;
                *(uint32_t*)(lp + rb1 + d) = lo_;
            }
        }
    }
#undef LOAD_STAGE
}

// ======================= Flash attention via mma.sync =======================
// 128 threads (4 warps), CTA = 64 Q-rows x (b,h); warp = 16 Q rows.
// S = Qhi/lo @ K^T hi/lo (bf16x3), online softmax, P split in-register,
// O += Phi Vhi + Plo Vhi + Phi Vlo. ctx written as bf16 hi/lo.
#define FROW 272
#define FQH  0
#define FQL  17408
#define FKH  34816
#define FKL  52224
#define FVH  69632
#define FVL  87040
#define FLASH_SMEM 104448

__global__ __launch_bounds__(128, 1)
void flash_mma_kernel(const __nv_bfloat16* __restrict__ qh,
                      const __nv_bfloat16* __restrict__ ql,
                      const __nv_bfloat16* __restrict__ kh,
                      const __nv_bfloat16* __restrict__ kl,
                      const __nv_bfloat16* __restrict__ vh,
                      const __nv_bfloat16* __restrict__ vl,
                      __nv_bfloat16* __restrict__ ch,
                      __nv_bfloat16* __restrict__ cl)
{
    extern __shared__ __align__(128) char fsm[];
    const uint32_t sb = smem_u32(fsm);
    const int bh = blockIdx.x;
    const int q0 = blockIdx.y << 6;
    const int tid  = threadIdx.x;
    const int lane = tid & 31;
    const int warp = tid >> 5;

    const char* qhg = (const char*)(qh + (size_t)bh * 131072 + (size_t)q0 * 128);
    const char* qlg = (const char*)(ql + (size_t)bh * 131072 + (size_t)q0 * 128);
    const char* khg = (const char*)(kh + (size_t)bh * 131072);
    const char* klg = (const char*)(kl + (size_t)bh * 131072);
    const char* vhg = (const char*)(vh + (size_t)bh * 131072);
    const char* vlg = (const char*)(vl + (size_t)bh * 131072);

    // load Q hi/lo (64 rows x 256B each)
    for (int i = tid; i < 2048; i += 128) {
        int mat = i >> 10, r = (i >> 4) & 63, c = (i & 15) << 4;
        const char* src = (mat ? qlg : qhg) + (size_t)r * 256 + c;
        cp16(sb + mat * 17408 + r * FROW + c, src);
    }
    cp_commit();

    float o[16][4];
#pragma unroll
    for (int i = 0; i < 16; ++i)
#pragma unroll
        for (int j = 0; j < 4; ++j) o[i][j] = 0.f;
    float m0_ = -INFINITY, m1_ = -INFINITY, l0_ = 0.f, l1_ = 0.f;

    // ldmatrix per-lane offsets
    const uint32_t a_off  = (lane & 15) * FROW + (lane >> 4) * 16;
    const uint32_t kb_off = ((lane & 7) + ((lane >> 4) & 1) * 8) * FROW
                          + ((lane >> 3) & 1) * 16;
    const uint32_t vb_off = ((lane & 7) + ((lane >> 3) & 1) * 8) * FROW
                          + ((lane >> 4) & 1) * 16;
    const uint32_t qbase = sb + FQH + warp * 16 * FROW;

    for (int kv0 = 0; kv0 < SEQ; kv0 += 64) {
        __syncthreads();                 // previous tile fully consumed
        for (int i = tid; i < 4096; i += 128) {
            int mat = i >> 10, r = (i >> 4) & 63, c = (i & 15) << 4;
            const char* g = (mat == 0 ? khg : mat == 1 ? klg :
                             mat == 2 ? vhg : vlg) + (size_t)(kv0 + r) * 256 + c;
            cp16(sb + FKH + mat * 17408 + r * FROW + c, g);
        }
        cp_commit();
        cp_wait0();
        __syncthreads();

        // ---- S = Q K^T (16 x 64 per warp) ----
        float s[8][4];
#pragma unroll
        for (int n = 0; n < 8; ++n)
#pragma unroll
            for (int r = 0; r < 4; ++r) s[n][r] = 0.f;

#pragma unroll
        for (int k = 0; k < 8; ++k) {
            uint32_t qhf[4], qlf[4];
            ldsm_x4(qhf, qbase + k * 32 + a_off);
            ldsm_x4(qlf, qbase + 17408 + k * 32 + a_off);
#pragma unroll
            for (int np = 0; np < 4; ++np) {
                uint32_t kbh[4], kbl[4];
                uint32_t kb = sb + FKH + np * 16 * FROW + k * 32 + kb_off;
                ldsm_x4(kbh, kb);
                ldsm_x4(kbl, kb + 17408);
                mma2(s[2 * np],     qhf, kbh[0], kbh[1]);
                mma2(s[2 * np],     qhf, kbl[0], kbl[1]);
                mma2(s[2 * np],     qlf, kbh[0], kbh[1]);
                mma2(s[2 * np + 1], qhf, kbh[2], kbh[3]);
                mma2(s[2 * np + 1], qhf, kbl[2], kbl[3]);
                mma2(s[2 * np + 1], qlf, kbh[2], kbh[3]);
            }
        }

        // ---- online softmax (rows g=lane>>2 and g+8) ----
        float mx0 = -INFINITY, mx1 = -INFINITY;
#pragma unroll
        for (int n = 0; n < 8; ++n) {
            mx0 = fmaxf(mx0, fmaxf(s[n][0], s[n][1]));
            mx1 = fmaxf(mx1, fmaxf(s[n][2], s[n][3]));
        }
        mx0 = fmaxf(mx0, __shfl_xor_sync(0xffffffffu, mx0, 1));
        mx0 = fmaxf(mx0, __shfl_xor_sync(0xffffffffu, mx0, 2));
        mx1 = fmaxf(mx1, __shfl_xor_sync(0xffffffffu, mx1, 1));
        mx1 = fmaxf(mx1, __shfl_xor_sync(0xffffffffu, mx1, 2));
        float mn0 = fmaxf(m0_, mx0), mn1 = fmaxf(m1_, mx1);
        float al0 = __expf(m0_ - mn0), al1 = __expf(m1_ - mn1);
        m0_ = mn0; m1_ = mn1;
        float sum0 = 0.f, sum1 = 0.f;
#pragma unroll
        for (int n = 0; n < 8; ++n) {
            s[n][0] = __expf(s[n][0] - mn0);
            s[n][1] = __expf(s[n][1] - mn0);
            s[n][2] = __expf(s[n][2] - mn1);
            s[n][3] = __expf(s[n][3] - mn1);
            sum0 += s[n][0] + s[n][1];
            sum1 += s[n][2] + s[n][3];
        }
        sum0 += __shfl_xor_sync(0xffffffffu, sum0, 1);
        sum0 += __shfl_xor_sync(0xffffffffu, sum0, 2);
        sum1 += __shfl_xor_sync(0xffffffffu, sum1, 1);
        sum1 += __shfl_xor_sync(0xffffffffu, sum1, 2);
        l0_ = l0_ * al0 + sum0;
        l1_ = l1_ * al1 + sum1;
#pragma unroll
        for (int i = 0; i < 16; ++i) {
            o[i][0] *= al0; o[i][1] *= al0;
            o[i][2] *= al1; o[i][3] *= al1;
        }

        // ---- pack P into A fragments (hi/lo) in-register ----
        uint32_t phi[4][4], plo[4][4];
#pragma unroll
        for (int kk = 0; kk < 4; ++kk) {
            int a = 2 * kk, b2 = 2 * kk + 1;
            phi[kk][0] = packpair(s[a][0],  s[a][1],  plo[kk][0]);
            phi[kk][1] = packpair(s[a][2],  s[a][3],  plo[kk][1]);
            phi[kk][2] = packpair(s[b2][0], s[b2][1], plo[kk][2]);
            phi[kk][3] = packpair(s[b2][2], s[b2][3], plo[kk][3]);
        }

        // ---- O += P V ----
#pragma unroll
        for (int kk = 0; kk < 4; ++kk) {
#pragma unroll
            for (int dp = 0; dp < 8; ++dp) {
                uint32_t vbh[4], vbl[4];
                uint32_t vb = sb + FVH + kk * 16 * FROW + dp * 32 + vb_off;
                ldsm_x4t(vbh, vb);
                ldsm_x4t(vbl, vb + 17408);
                mma2(o[2 * dp],     phi[kk], vbh[0], vbh[1]);
                mma2(o[2 * dp],     plo[kk], vbh[0], vbh[1]);
                mma2(o[2 * dp],     phi[kk], vbl[0], vbl[1]);
                mma2(o[2 * dp + 1], phi[kk], vbh[2], vbh[3]);
                mma2(o[2 * dp + 1], plo[kk], vbh[2], vbh[3]);
                mma2(o[2 * dp + 1], phi[kk], vbl[2], vbl[3]);
            }
        }
    }

    // ---- epilogue: normalize, split to bf16 hi/lo ctx [tok][E] ----
    const int g = lane >> 2, t = lane & 3;
    const int b  = bh >> 4, h = bh & 15;
    const float inv0 = 1.f / l0_, inv1 = 1.f / l1_;
    const size_t tok0 = (size_t)(b * SEQ + q0 + warp * 16 + g);
    const size_t tok1 = tok0 + 8;
#pragma unroll
    for (int dn = 0; dn < 16; ++dn) {
        int e = h * 128 + dn * 8 + 2 * t;
        uint32_t lo_;
        uint32_t hi_ = packpair(o[dn][0] * inv0, o[dn][1] * inv0, lo_);
        *(uint32_t*)(ch + tok0 * EMB + e) = hi_;
        *(uint32_t*)(cl + tok0 * EMB + e) = lo_;
        hi_ = packpair(o[dn][2] * inv1, o[dn][3] * inv1, lo_);
        *(uint32_t*)(ch + tok1 * EMB + e) = hi_;
        *(uint32_t*)(cl + tok1 * EMB + e) = lo_;
    }
}

// ======================= Launch =============================================
extern "C" void kernel_launch(void* const* d_in, const int* in_sizes, int n_in,
                              void* d_out, int out_size)
{
    (void)in_sizes; (void)n_in; (void)out_size;
    const float* x     = (const float*)d_in[0];
    const float* w_in  = (const float*)d_in[1];
    const float* b_in  = (const float*)d_in[2];
    const float* w_out = (const float*)d_in[3];
    const float* b_out = (const float*)d_in[4];
    float* out = (float*)d_out;

    __nv_bfloat16 *qhp,*qlp,*khp,*klp,*vhp,*vlp,*chp,*clp;
    __nv_bfloat16 *xh,*xl,*wih,*wil,*woh,*wol;
    cudaGetSymbolAddress((void**)&qhp, g_qh);
    cudaGetSymbolAddress((void**)&qlp, g_ql);
    cudaGetSymbolAddress((void**)&khp, g_kh);
    cudaGetSymbolAddress((void**)&klp, g_kl);
    cudaGetSymbolAddress((void**)&vhp, g_vh);
    cudaGetSymbolAddress((void**)&vlp, g_vl);
    cudaGetSymbolAddress((void**)&chp, g_ch);
    cudaGetSymbolAddress((void**)&clp, g_cl);
    cudaGetSymbolAddress((void**)&xh,  g_x_hi);
    cudaGetSymbolAddress((void**)&xl,  g_x_lo);
    cudaGetSymbolAddress((void**)&wih, g_wi_hi);
    cudaGetSymbolAddress((void**)&wil, g_wi_lo);
    cudaGetSymbolAddress((void**)&woh, g_wo_hi);
    cudaGetSymbolAddress((void**)&wol, g_wo_lo);

    cudaFuncSetAttribute(mma_gemm_kernel,
                         cudaFuncAttributeMaxDynamicSharedMemorySize, GEMM_SMEM);
    cudaFuncSetAttribute(flash_mma_kernel,
                         cudaFuncAttributeMaxDynamicSharedMemorySize, FLASH_SMEM);

    // bf16 hi/lo splits of inputs
    {
        int n4 = MTOK * EMB / 4;
        split_bf16_kernel<<<n4 / 256, 256>>>((const float4*)x,
            (__nv_bfloat162*)xh, (__nv_bfloat162*)xl, n4);
    }
    {
        int n4 = QKVN * EMB / 4;
        split_bf16_kernel<<<n4 / 256, 256>>>((const float4*)w_in,
            (__nv_bfloat162*)wih, (__nv_bfloat162*)wil, n4);
    }
    {
        int n4 = EMB * EMB / 4;
        split_bf16_kernel<<<n4 / 256, 256>>>((const float4*)w_out,
            (__nv_bfloat162*)woh, (__nv_bfloat162*)wol, n4);
    }

    // 1) QKV projection -> bf16 hi/lo [B,H,S,D] (q pre-scaled)
    {
        dim3 g(QKVN / 128, MTOK / 128);
        mma_gemm_kernel<<<g, 256, GEMM_SMEM>>>(xh, xl, wih, wil, b_in,
            nullptr, qhp, qlp, khp, klp, vhp, vlp, QKVN, EMB, 1);
    }

    // 2) flash attention (tensor cores) -> ctx bf16 hi/lo [tok][E]
    {
        dim3 g(BATCH * HEADS, SEQ / 64);
        flash_mma_kernel<<<g, 128, FLASH_SMEM>>>(qhp, qlp, khp, klp, vhp, vlp,
                                                 chp, clp);
    }

    // 3) output projection (fp32 out)
    {
        dim3 g(EMB / 128, MTOK / 128);
        mma_gemm_kernel<<<g, 256, GEMM_SMEM>>>(chp, clp, woh, wol, b_out,
            out, nullptr, nullptr, nullptr, nullptr, nullptr, nullptr,
            EMB, EMB, 0);
    }
}

// round 6
// speedup vs baseline: 2.7960x; 1.1108x over previous
#include <cuda_runtime.h>
#include <cuda_bf16.h>
#include <math.h>
#include <stdint.h>

#define BATCH 4
#define SEQ   1024
#define EMB   2048
#define HEADS 16
#define HDIM  128
#define MTOK  4096
#define QKVN  6144

// Scratch (device globals: no cudaMalloc allowed)
__device__ __nv_bfloat16 g_qh[8388608];
__device__ __nv_bfloat16 g_ql[8388608];
__device__ __nv_bfloat16 g_kh[8388608];
__device__ __nv_bfloat16 g_kl[8388608];
__device__ __nv_bfloat16 g_vh[8388608];
__device__ __nv_bfloat16 g_vl[8388608];
__device__ __nv_bfloat16 g_ch[8388608];
__device__ __nv_bfloat16 g_cl[8388608];
__device__ __nv_bfloat16 g_x_hi[8388608];
__device__ __nv_bfloat16 g_x_lo[8388608];
__device__ __nv_bfloat16 g_wi_hi[12582912];
__device__ __nv_bfloat16 g_wi_lo[12582912];
__device__ __nv_bfloat16 g_wo_hi[4194304];
__device__ __nv_bfloat16 g_wo_lo[4194304];

// ======================= helpers ============================================
__device__ __forceinline__ uint32_t smem_u32(const void* p) {
    uint32_t a;
    asm("{ .reg .u64 t; cvta.to.shared.u64 t, %1; cvt.u32.u64 %0, t; }"
        : "=r"(a) : "l"(p));
    return a;
}
__device__ __forceinline__ void cp16(uint32_t dst, const void* src) {
    asm volatile("cp.async.cg.shared.global [%0], [%1], 16;"
                 :: "r"(dst), "l"(src) : "memory");
}
__device__ __forceinline__ void cp_commit() {
    asm volatile("cp.async.commit_group;" ::: "memory");
}
__device__ __forceinline__ void cp_wait1() {
    asm volatile("cp.async.wait_group 1;" ::: "memory");
}
__device__ __forceinline__ void cp_wait0() {
    asm volatile("cp.async.wait_group 0;" ::: "memory");
}
__device__ __forceinline__ void ldsm_x4(uint32_t (&r)[4], uint32_t a) {
    asm volatile("ldmatrix.sync.aligned.m8n8.x4.shared.b16 {%0,%1,%2,%3}, [%4];"
                 : "=r"(r[0]), "=r"(r[1]), "=r"(r[2]), "=r"(r[3]) : "r"(a));
}
__device__ __forceinline__ void ldsm_x4t(uint32_t (&r)[4], uint32_t a) {
    asm volatile("ldmatrix.sync.aligned.m8n8.x4.trans.shared.b16 {%0,%1,%2,%3}, [%4];"
                 : "=r"(r[0]), "=r"(r[1]), "=r"(r[2]), "=r"(r[3]) : "r"(a));
}
__device__ __forceinline__ void mma2(float (&d)[4], const uint32_t (&a)[4],
                                     uint32_t b0, uint32_t b1) {
    asm volatile(
        "mma.sync.aligned.m16n8k16.row.col.f32.bf16.bf16.f32 "
        "{%0,%1,%2,%3}, {%4,%5,%6,%7}, {%8,%9}, {%0,%1,%2,%3};"
        : "+f"(d[0]), "+f"(d[1]), "+f"(d[2]), "+f"(d[3])
        : "r"(a[0]), "r"(a[1]), "r"(a[2]), "r"(a[3]), "r"(b0), "r"(b1));
}
// pack (x,y) -> bf16x2 hi, residual bf16x2 lo
__device__ __forceinline__ uint32_t packpair(float x, float y, uint32_t& lo) {
    __nv_bfloat16 hx = __float2bfloat16_rn(x);
    __nv_bfloat16 hy = __float2bfloat16_rn(y);
    __nv_bfloat162 h(hx, hy);
    __nv_bfloat162 l(__float2bfloat16_rn(x - __bfloat162float(hx)),
                     __float2bfloat16_rn(y - __bfloat162float(hy)));
    lo = *(uint32_t*)&l;
    return *(uint32_t*)&h;
}

// ======================= bf16 hi/lo split ===================================
__global__ void split_bf16_kernel(const float4* __restrict__ in,
                                  __nv_bfloat162* __restrict__ hi,
                                  __nv_bfloat162* __restrict__ lo, int n4)
{
    int i = blockIdx.x * blockDim.x + threadIdx.x;
    if (i >= n4) return;
    float4 v = in[i];
    __nv_bfloat16 h0 = __float2bfloat16_rn(v.x);
    __nv_bfloat16 h1 = __float2bfloat16_rn(v.y);
    __nv_bfloat16 h2 = __float2bfloat16_rn(v.z);
    __nv_bfloat16 h3 = __float2bfloat16_rn(v.w);
    __nv_bfloat16 l0 = __float2bfloat16_rn(v.x - __bfloat162float(h0));
    __nv_bfloat16 l1 = __float2bfloat16_rn(v.y - __bfloat162float(h1));
    __nv_bfloat16 l2 = __float2bfloat16_rn(v.z - __bfloat162float(h2));
    __nv_bfloat16 l3 = __float2bfloat16_rn(v.w - __bfloat162float(h3));
    hi[2 * i]     = __nv_bfloat162(h0, h1);
    hi[2 * i + 1] = __nv_bfloat162(h2, h3);
    lo[2 * i]     = __nv_bfloat162(l0, l1);
    lo[2 * i + 1] = __nv_bfloat162(l2, l3);
}

// ======================= bf16x3 mma.sync GEMM-NT ============================
// 128x128 CTA tile, BK=32, 2-stage cp.async pipeline, 8 warps (64x32 each),
// 2 CTAs/SM. mode 0: fp32 C0 (+bias). mode 1: QKV -> bf16 hi/lo [B,H,S,D].
#define SROW    80
#define MATB    (128 * SROW)
#define STAGEB  (4 * MATB)               // 40960
#define GEMM_SMEM (2 * STAGEB)           // 81920

__global__ __launch_bounds__(256, 2)
void mma_gemm_kernel(const __nv_bfloat16* __restrict__ Ahi,
                     const __nv_bfloat16* __restrict__ Alo,
                     const __nv_bfloat16* __restrict__ Bhi,
                     const __nv_bfloat16* __restrict__ Blo,
                     const float* __restrict__ bias,
                     float* __restrict__ C0,
                     __nv_bfloat16* __restrict__ QHo, __nv_bfloat16* __restrict__ QLo,
                     __nv_bfloat16* __restrict__ KHo, __nv_bfloat16* __restrict__ KLo,
                     __nv_bfloat16* __restrict__ VHo, __nv_bfloat16* __restrict__ VLo,
                     int N, int K, int mode)
{
    extern __shared__ __align__(128) char smem[];
    const uint32_t sb = smem_u32(smem);
    const int tid  = threadIdx.x;
    const int lane = tid & 31;
    const int warp = tid >> 5;
    const int m0 = blockIdx.y << 7;
    const int n0 = blockIdx.x << 7;
    const int wm = (warp >> 2) << 6;
    const int wn = (warp & 3) << 5;
    const int KT = K >> 5;

    const char* gsrc0 = (const char*)(Ahi + (size_t)m0 * K);
    const char* gsrc1 = (const char*)(Alo + (size_t)m0 * K);
    const char* gsrc2 = (const char*)(Bhi + (size_t)n0 * K);
    const char* gsrc3 = (const char*)(Blo + (size_t)n0 * K);
    const size_t grs = (size_t)K * 2;

    const int lr  = tid >> 2;
    const int lch = (tid & 3) << 4;

#define LOAD_STAGE(t, slot) do {                                             \
    const uint32_t base_ = sb + (slot) * STAGEB;                             \
    const size_t koff_ = (size_t)(t) * 64;                                   \
    const char* gs_[4] = { gsrc0, gsrc1, gsrc2, gsrc3 };                     \
    _Pragma("unroll")                                                        \
    for (int mx_ = 0; mx_ < 4; ++mx_) {                                      \
        uint32_t mb_ = base_ + mx_ * MATB;                                   \
        cp16(mb_ + lr * SROW + lch,                                          \
             gs_[mx_] + (size_t)lr * grs + koff_ + lch);                     \
        cp16(mb_ + (lr + 64) * SROW + lch,                                   \
             gs_[mx_] + (size_t)(lr + 64) * grs + koff_ + lch);              \
    }                                                                        \
} while (0)

    float acc[4][4][4];
#pragma unroll
    for (int i = 0; i < 4; ++i)
#pragma unroll
        for (int j = 0; j < 4; ++j)
#pragma unroll
            for (int r = 0; r < 4; ++r) acc[i][j][r] = 0.f;

    // ldmatrix per-lane offsets
    const uint32_t a_off = (uint32_t)((lane & 15) * SROW + (lane >> 4) * 16);
    const uint32_t b_off = (uint32_t)(((lane & 7) + ((lane >> 4) & 1) * 8) * SROW
                                      + ((lane >> 3) & 1) * 16);

    // prologue: fill both stages
    LOAD_STAGE(0, 0); cp_commit();
    LOAD_STAGE(1, 1); cp_commit();

    for (int t = 0; t < KT; ++t) {
        cp_wait1();                       // stage t resident
        __syncthreads();

        const uint32_t slot = sb + (t & 1) * STAGEB;
#pragma unroll
        for (int s = 0; s < 2; ++s) {
            const uint32_t ks = s * 32;
            // B fragments: 16 rows per ldsm_x4 (2 n8-tiles, both k-halves)
            uint32_t bH[2][4], bL[2][4];
#pragma unroll
            for (int jp = 0; jp < 2; ++jp) {
                uint32_t bd = slot + 2 * MATB + (wn + jp * 16) * SROW + ks + b_off;
                ldsm_x4(bH[jp], bd);
                ldsm_x4(bL[jp], bd + MATB);
            }
#pragma unroll
            for (int i = 0; i < 4; ++i) {
                uint32_t aH[4], aL[4];
                uint32_t ad = slot + (wm + i * 16) * SROW + ks + a_off;
                ldsm_x4(aH, ad);
                ldsm_x4(aL, ad + MATB);
#pragma unroll
                for (int jp = 0; jp < 2; ++jp) {
                    mma2(acc[i][2 * jp],     aH, bH[jp][0], bH[jp][1]);
                    mma2(acc[i][2 * jp],     aH, bL[jp][0], bL[jp][1]);
                    mma2(acc[i][2 * jp],     aL, bH[jp][0], bH[jp][1]);
                    mma2(acc[i][2 * jp + 1], aH, bH[jp][2], bH[jp][3]);
                    mma2(acc[i][2 * jp + 1], aH, bL[jp][2], bL[jp][3]);
                    mma2(acc[i][2 * jp + 1], aL, bH[jp][2], bH[jp][3]);
                }
            }
        }
        __syncthreads();                  // all reads of slot t done
        if (t + 2 < KT) LOAD_STAGE(t + 2, t & 1);
        cp_commit();                      // always commit (count invariant)
    }

    // ---------------- epilogue ----------------
    const int r0 = lane >> 2;
    const int c0 = (lane & 3) << 1;
    float bj[4][2];
#pragma unroll
    for (int j = 0; j < 4; ++j) {
        int nc = n0 + wn + j * 8 + c0;
        bj[j][0] = __ldg(&bias[nc]);
        bj[j][1] = __ldg(&bias[nc + 1]);
    }

    if (mode == 0) {
#pragma unroll
        for (int i = 0; i < 4; ++i) {
            int mr = m0 + wm + i * 16 + r0;
#pragma unroll
            for (int j = 0; j < 4; ++j) {
                int nc = n0 + wn + j * 8 + c0;
                float2 v0 = make_float2(acc[i][j][0] + bj[j][0],
                                        acc[i][j][1] + bj[j][1]);
                float2 v1 = make_float2(acc[i][j][2] + bj[j][0],
                                        acc[i][j][3] + bj[j][1]);
                *(float2*)&C0[(size_t)mr * N + nc]       = v0;
                *(float2*)&C0[(size_t)(mr + 8) * N + nc] = v1;
            }
        }
    } else {
        const int part = n0 >> 11;
        const int hh   = (n0 >> 7) & 15;
        __nv_bfloat16 *hp, *lp;
        float scl = 1.f;
        if (part == 0) { hp = QHo; lp = QLo; scl = 0.088388347648318447f; }
        else if (part == 1) { hp = KHo; lp = KLo; }
        else { hp = VHo; lp = VLo; }
#pragma unroll
        for (int i = 0; i < 4; ++i) {
            int mr = m0 + wm + i * 16 + r0;
            int bb = mr >> 10, ss = mr & 1023;
            size_t rb0 = (((size_t)(bb * HEADS + hh) * SEQ) + ss) << 7;
            int mr8 = mr + 8;
            int bb8 = mr8 >> 10, ss8 = mr8 & 1023;
            size_t rb1 = (((size_t)(bb8 * HEADS + hh) * SEQ) + ss8) << 7;
#pragma unroll
            for (int j = 0; j < 4; ++j) {
                int d = wn + j * 8 + c0;
                uint32_t lo_;
                uint32_t hi_ = packpair((acc[i][j][0] + bj[j][0]) * scl,
                                        (acc[i][j][1] + bj[j][1]) * scl, lo_);
                *(uint32_t*)(hp + rb0 + d) = hi_;
                *(uint32_t*)(lp + rb0 + d) = lo_;
                hi_ = packpair((acc[i][j][2] + bj[j][0]) * scl,
                               (acc[i][j][3] + bj[j][1]) * scl, lo_);
                *(uint32_t*)(hp + rb1 + d) = hi_;
                *(uint32_t*)(lp + rb1 + d) = lo_;
            }
        }
    }
#undef LOAD_STAGE
}

// ======================= Flash attention via mma.sync =======================
#define FROW 272
#define FQH  0
#define FQL  17408
#define FKH  34816
#define FKL  52224
#define FVH  69632
#define FVL  87040
#define FLASH_SMEM 104448

__global__ __launch_bounds__(128, 1)
void flash_mma_kernel(const __nv_bfloat16* __restrict__ qh,
                      const __nv_bfloat16* __restrict__ ql,
                      const __nv_bfloat16* __restrict__ kh,
                      const __nv_bfloat16* __restrict__ kl,
                      const __nv_bfloat16* __restrict__ vh,
                      const __nv_bfloat16* __restrict__ vl,
                      __nv_bfloat16* __restrict__ ch,
                      __nv_bfloat16* __restrict__ cl)
{
    extern __shared__ __align__(128) char fsm[];
    const uint32_t sb = smem_u32(fsm);
    const int bh = blockIdx.x;
    const int q0 = blockIdx.y << 6;
    const int tid  = threadIdx.x;
    const int lane = tid & 31;
    const int warp = tid >> 5;

    const char* qhg = (const char*)(qh + (size_t)bh * 131072 + (size_t)q0 * 128);
    const char* qlg = (const char*)(ql + (size_t)bh * 131072 + (size_t)q0 * 128);
    const char* khg = (const char*)(kh + (size_t)bh * 131072);
    const char* klg = (const char*)(kl + (size_t)bh * 131072);
    const char* vhg = (const char*)(vh + (size_t)bh * 131072);
    const char* vlg = (const char*)(vl + (size_t)bh * 131072);

    for (int i = tid; i < 2048; i += 128) {
        int mat = i >> 10, r = (i >> 4) & 63, c = (i & 15) << 4;
        const char* src = (mat ? qlg : qhg) + (size_t)r * 256 + c;
        cp16(sb + mat * 17408 + r * FROW + c, src);
    }
    cp_commit();

    float o[16][4];
#pragma unroll
    for (int i = 0; i < 16; ++i)
#pragma unroll
        for (int j = 0; j < 4; ++j) o[i][j] = 0.f;
    float m0_ = -INFINITY, m1_ = -INFINITY, l0_ = 0.f, l1_ = 0.f;

    const uint32_t a_off  = (lane & 15) * FROW + (lane >> 4) * 16;
    const uint32_t kb_off = ((lane & 7) + ((lane >> 4) & 1) * 8) * FROW
                          + ((lane >> 3) & 1) * 16;
    const uint32_t vb_off = ((lane & 7) + ((lane >> 3) & 1) * 8) * FROW
                          + ((lane >> 4) & 1) * 16;
    const uint32_t qbase = sb + FQH + warp * 16 * FROW;

    for (int kv0 = 0; kv0 < SEQ; kv0 += 64) {
        __syncthreads();
        for (int i = tid; i < 4096; i += 128) {
            int mat = i >> 10, r = (i >> 4) & 63, c = (i & 15) << 4;
            const char* g = (mat == 0 ? khg : mat == 1 ? klg :
                             mat == 2 ? vhg : vlg) + (size_t)(kv0 + r) * 256 + c;
            cp16(sb + FKH + mat * 17408 + r * FROW + c, g);
        }
        cp_commit();
        cp_wait0();
        __syncthreads();

        float s[8][4];
#pragma unroll
        for (int n = 0; n < 8; ++n)
#pragma unroll
            for (int r = 0; r < 4; ++r) s[n][r] = 0.f;

#pragma unroll
        for (int k = 0; k < 8; ++k) {
            uint32_t qhf[4], qlf[4];
            ldsm_x4(qhf, qbase + k * 32 + a_off);
            ldsm_x4(qlf, qbase + 17408 + k * 32 + a_off);
#pragma unroll
            for (int np = 0; np < 4; ++np) {
                uint32_t kbh[4], kbl[4];
                uint32_t kb = sb + FKH + np * 16 * FROW + k * 32 + kb_off;
                ldsm_x4(kbh, kb);
                ldsm_x4(kbl, kb + 17408);
                mma2(s[2 * np],     qhf, kbh[0], kbh[1]);
                mma2(s[2 * np],     qhf, kbl[0], kbl[1]);
                mma2(s[2 * np],     qlf, kbh[0], kbh[1]);
                mma2(s[2 * np + 1], qhf, kbh[2], kbh[3]);
                mma2(s[2 * np + 1], qhf, kbl[2], kbl[3]);
                mma2(s[2 * np + 1], qlf, kbh[2], kbh[3]);
            }
        }

        float mx0 = -INFINITY, mx1 = -INFINITY;
#pragma unroll
        for (int n = 0; n < 8; ++n) {
            mx0 = fmaxf(mx0, fmaxf(s[n][0], s[n][1]));
            mx1 = fmaxf(mx1, fmaxf(s[n][2], s[n][3]));
        }
        mx0 = fmaxf(mx0, __shfl_xor_sync(0xffffffffu, mx0, 1));
        mx0 = fmaxf(mx0, __shfl_xor_sync(0xffffffffu, mx0, 2));
        mx1 = fmaxf(mx1, __shfl_xor_sync(0xffffffffu, mx1, 1));
        mx1 = fmaxf(mx1, __shfl_xor_sync(0xffffffffu, mx1, 2));
        float mn0 = fmaxf(m0_, mx0), mn1 = fmaxf(m1_, mx1);
        float al0 = __expf(m0_ - mn0), al1 = __expf(m1_ - mn1);
        m0_ = mn0; m1_ = mn1;
        float sum0 = 0.f, sum1 = 0.f;
#pragma unroll
        for (int n = 0; n < 8; ++n) {
            s[n][0] = __expf(s[n][0] - mn0);
            s[n][1] = __expf(s[n][1] - mn0);
            s[n][2] = __expf(s[n][2] - mn1);
            s[n][3] = __expf(s[n][3] - mn1);
            sum0 += s[n][0] + s[n][1];
            sum1 += s[n][2] + s[n][3];
        }
        sum0 += __shfl_xor_sync(0xffffffffu, sum0, 1);
        sum0 += __shfl_xor_sync(0xffffffffu, sum0, 2);
        sum1 += __shfl_xor_sync(0xffffffffu, sum1, 1);
        sum1 += __shfl_xor_sync(0xffffffffu, sum1, 2);
        l0_ = l0_ * al0 + sum0;
        l1_ = l1_ * al1 + sum1;
#pragma unroll
        for (int i = 0; i < 16; ++i) {
            o[i][0] *= al0; o[i][1] *= al0;
            o[i][2] *= al1; o[i][3] *= al1;
        }

        uint32_t phi[4][4], plo[4][4];
#pragma unroll
        for (int kk = 0; kk < 4; ++kk) {
            int a = 2 * kk, b2 = 2 * kk + 1;
            phi[kk][0] = packpair(s[a][0],  s[a][1],  plo[kk][0]);
            phi[kk][1] = packpair(s[a][2],  s[a][3],  plo[kk][1]);
            phi[kk][2] = packpair(s[b2][0], s[b2][1], plo[kk][2]);
            phi[kk][3] = packpair(s[b2][2], s[b2][3], plo[kk][3]);
        }

#pragma unroll
        for (int kk = 0; kk < 4; ++kk) {
#pragma unroll
            for (int dp = 0; dp < 8; ++dp) {
                uint32_t vbh[4], vbl[4];
                uint32_t vb = sb + FVH + kk * 16 * FROW + dp * 32 + vb_off;
                ldsm_x4t(vbh, vb);
                ldsm_x4t(vbl, vb + 17408);
                mma2(o[2 * dp],     phi[kk], vbh[0], vbh[1]);
                mma2(o[2 * dp],     plo[kk], vbh[0], vbh[1]);
                mma2(o[2 * dp],     phi[kk], vbl[0], vbl[1]);
                mma2(o[2 * dp + 1], phi[kk], vbh[2], vbh[3]);
                mma2(o[2 * dp + 1], plo[kk], vbh[2], vbh[3]);
                mma2(o[2 * dp + 1], phi[kk], vbl[2], vbl[3]);
            }
        }
    }

    const int g = lane >> 2, t = lane & 3;
    const int b  = bh >> 4, h = bh & 15;
    const float inv0 = 1.f / l0_, inv1 = 1.f / l1_;
    const size_t tok0 = (size_t)(b * SEQ + q0 + warp * 16 + g);
    const size_t tok1 = tok0 + 8;
#pragma unroll
    for (int dn = 0; dn < 16; ++dn) {
        int e = h * 128 + dn * 8 + 2 * t;
        uint32_t lo_;
        uint32_t hi_ = packpair(o[dn][0] * inv0, o[dn][1] * inv0, lo_);
        *(uint32_t*)(ch + tok0 * EMB + e) = hi_;
        *(uint32_t*)(cl + tok0 * EMB + e) = lo_;
        hi_ = packpair(o[dn][2] * inv1, o[dn][3] * inv1, lo_);
        *(uint32_t*)(ch + tok1 * EMB + e) = hi_;
        *(uint32_t*)(cl + tok1 * EMB + e) = lo_;
    }
}

// ======================= Launch =============================================
extern "C" void kernel_launch(void* const* d_in, const int* in_sizes, int n_in,
                              void* d_out, int out_size)
{
    (void)in_sizes; (void)n_in; (void)out_size;
    const float* x     = (const float*)d_in[0];
    const float* w_in  = (const float*)d_in[1];
    const float* b_in  = (const float*)d_in[2];
    const float* w_out = (const float*)d_in[3];
    const float* b_out = (const float*)d_in[4];
    float* out = (float*)d_out;

    __nv_bfloat16 *qhp,*qlp,*khp,*klp,*vhp,*vlp,*chp,*clp;
    __nv_bfloat16 *xh,*xl,*wih,*wil,*woh,*wol;
    cudaGetSymbolAddress((void**)&qhp, g_qh);
    cudaGetSymbolAddress((void**)&qlp, g_ql);
    cudaGetSymbolAddress((void**)&khp, g_kh);
    cudaGetSymbolAddress((void**)&klp, g_kl);
    cudaGetSymbolAddress((void**)&vhp, g_vh);
    cudaGetSymbolAddress((void**)&vlp, g_vl);
    cudaGetSymbolAddress((void**)&chp, g_ch);
    cudaGetSymbolAddress((void**)&clp, g_cl);
    cudaGetSymbolAddress((void**)&xh,  g_x_hi);
    cudaGetSymbolAddress((void**)&xl,  g_x_lo);
    cudaGetSymbolAddress((void**)&wih, g_wi_hi);
    cudaGetSymbolAddress((void**)&wil, g_wi_lo);
    cudaGetSymbolAddress((void**)&woh, g_wo_hi);
    cudaGetSymbolAddress((void**)&wol, g_wo_lo);

    cudaFuncSetAttribute(mma_gemm_kernel,
                         cudaFuncAttributeMaxDynamicSharedMemorySize, GEMM_SMEM);
    cudaFuncSetAttribute(flash_mma_kernel,
                         cudaFuncAttributeMaxDynamicSharedMemorySize, FLASH_SMEM);

    {
        int n4 = MTOK * EMB / 4;
        split_bf16_kernel<<<n4 / 256, 256>>>((const float4*)x,
            (__nv_bfloat162*)xh, (__nv_bfloat162*)xl, n4);
    }
    {
        int n4 = QKVN * EMB / 4;
        split_bf16_kernel<<<n4 / 256, 256>>>((const float4*)w_in,
            (__nv_bfloat162*)wih, (__nv_bfloat162*)wil, n4);
    }
    {
        int n4 = EMB * EMB / 4;
        split_bf16_kernel<<<n4 / 256, 256>>>((const float4*)w_out,
            (__nv_bfloat162*)woh, (__nv_bfloat162*)wol, n4);
    }

    // 1) QKV projection -> bf16 hi/lo [B,H,S,D] (q pre-scaled)
    {
        dim3 g(QKVN / 128, MTOK / 128);
        mma_gemm_kernel<<<g, 256, GEMM_SMEM>>>(xh, xl, wih, wil, b_in,
            nullptr, qhp, qlp, khp, klp, vhp, vlp, QKVN, EMB, 1);
    }

    // 2) flash attention -> ctx bf16 hi/lo [tok][E]
    {
        dim3 g(BATCH * HEADS, SEQ / 64);
        flash_mma_kernel<<<g, 128, FLASH_SMEM>>>(qhp, qlp, khp, klp, vhp, vlp,
                                                 chp, clp);
    }

    // 3) output projection (fp32 out)
    {
        dim3 g(EMB / 128, MTOK / 128);
        mma_gemm_kernel<<<g, 256, GEMM_SMEM>>>(chp, clp, woh, wol, b_out,
            out, nullptr, nullptr, nullptr, nullptr, nullptr, nullptr,
            EMB, EMB, 0);
    }
}